// round 1
// baseline (speedup 1.0000x reference)
#include <cuda_runtime.h>

#define MAXN 100000

// ---------------- scratch (device globals, no allocation allowed) ----------
__device__ float g_h1[MAXN * 128];   // layer1 GEMM out [N, H*32]
__device__ float g_acc1[MAXN * 128]; // layer1 unnormalized aggregation
__device__ float g_hr[MAXN * 128];   // layer1 output after relu (layer2 input)
__device__ float g_as1[MAXN * 4];
__device__ float g_ad1[MAXN * 4];
__device__ float g_den1[MAXN * 4];
__device__ float g_h2[MAXN * 32];
__device__ float g_acc2[MAXN * 32];
__device__ float g_as2[MAXN];
__device__ float g_ad2[MAXN];
__device__ float g_den2[MAXN];

__device__ __forceinline__ float lrelu(float x) { return x > 0.f ? x : 0.2f * x; }

__device__ __forceinline__ void red_add_v4(float* p, float a, float b, float c, float d) {
    asm volatile("red.global.add.v4.f32 [%0], {%1,%2,%3,%4};"
                 :: "l"(p), "f"(a), "f"(b), "f"(c), "f"(d) : "memory");
}

// ---------------- GEMM: Y[n, nout] = X[n,128] @ W[128, nout] ---------------
// BM=64, BK=16, thread tile 4x4. BN template: 64 (layer1, grid.y=2) or 32.
template <int BN>
__global__ __launch_bounds__(16 * (BN / 4))
void gemm_k128(const float* __restrict__ X, const float* __restrict__ W,
               float* __restrict__ Y, int n, int nout) {
    constexpr int BM = 64, BK = 16;
    constexpr int T = 16 * (BN / 4);
    __shared__ float xs[BK][BM];
    __shared__ float ws[BK][BN];
    const int tid = threadIdx.x;
    const int row0 = blockIdx.x * BM;
    const int col0 = blockIdx.y * BN;
    const int tx = tid % (BN / 4);
    const int ty = tid / (BN / 4);
    float acc[4][4] = {};

    for (int k0 = 0; k0 < 128; k0 += BK) {
        // X tile (transposed into smem): 64 rows x 16 k = 256 float4
        #pragma unroll
        for (int idx = tid; idx < BM * BK / 4; idx += T) {
            int r = idx >> 2, q = idx & 3;
            int grow = row0 + r;
            float4 v = make_float4(0.f, 0.f, 0.f, 0.f);
            if (grow < n) v = *(const float4*)&X[grow * 128 + k0 + q * 4];
            xs[q * 4 + 0][r] = v.x; xs[q * 4 + 1][r] = v.y;
            xs[q * 4 + 2][r] = v.z; xs[q * 4 + 3][r] = v.w;
        }
        // W tile: 16 x BN
        #pragma unroll
        for (int idx = tid; idx < BK * BN / 4; idx += T) {
            int r = idx / (BN / 4), c = idx % (BN / 4);
            *(float4*)&ws[r][c * 4] = *(const float4*)&W[(k0 + r) * nout + col0 + c * 4];
        }
        __syncthreads();
        #pragma unroll
        for (int kk = 0; kk < BK; kk++) {
            float4 a = *(const float4*)&xs[kk][ty * 4];
            float4 b = *(const float4*)&ws[kk][tx * 4];
            float av[4] = {a.x, a.y, a.z, a.w};
            float bv[4] = {b.x, b.y, b.z, b.w};
            #pragma unroll
            for (int i = 0; i < 4; i++)
                #pragma unroll
                for (int j = 0; j < 4; j++)
                    acc[i][j] += av[i] * bv[j];
        }
        __syncthreads();
    }
    #pragma unroll
    for (int i = 0; i < 4; i++) {
        int grow = row0 + ty * 4 + i;
        if (grow < n)
            *(float4*)&Y[grow * nout + col0 + tx * 4] =
                make_float4(acc[i][0], acc[i][1], acc[i][2], acc[i][3]);
    }
}

// -------- node prep: alpha_src/alpha_dst dots, fold self-loop into den/acc --
// 8 threads per (node,head) group; each handles 4 channels of the 32.
template <int H>
__global__ void node_prep(const float* __restrict__ h, const float* __restrict__ a_src,
                          const float* __restrict__ a_dst, float* __restrict__ as_,
                          float* __restrict__ ad_, float* __restrict__ den,
                          float* __restrict__ acc, int n) {
    int t = blockIdx.x * blockDim.x + threadIdx.x;
    int g = t >> 3;
    int sub = t & 7;
    bool valid = g < n * H;
    int gg = valid ? g : 0;
    int head = (H == 1) ? 0 : (gg & (H - 1));
    float4 hv = *(const float4*)&h[gg * 32 + sub * 4];
    float4 av = *(const float4*)&a_src[head * 32 + sub * 4];
    float4 dv = *(const float4*)&a_dst[head * 32 + sub * 4];
    float s = hv.x * av.x + hv.y * av.y + hv.z * av.z + hv.w * av.w;
    float d = hv.x * dv.x + hv.y * dv.y + hv.z * dv.z + hv.w * dv.w;
    #pragma unroll
    for (int o = 4; o; o >>= 1) {
        s += __shfl_xor_sync(0xffffffffu, s, o);
        d += __shfl_xor_sync(0xffffffffu, d, o);
    }
    float w = 0.f;
    if (sub == 0) w = __expf(lrelu(s + d));
    w = __shfl_sync(0xffffffffu, w, threadIdx.x & 24);  // broadcast from group lane0
    if (valid) {
        if (sub == 0) { as_[gg] = s; ad_[gg] = d; den[gg] = w; }
        *(float4*)&acc[gg * 32 + sub * 4] =
            make_float4(hv.x * w, hv.y * w, hv.z * w, hv.w * w);
    }
}

// -------- edge pass, layer 1 (H=4, C=32): one warp per edge -----------------
__global__ void edge_pass4(const int* __restrict__ src, const int* __restrict__ dst, int E,
                           const float* __restrict__ as_, const float* __restrict__ ad_,
                           float* __restrict__ den, const float* __restrict__ h,
                           float* __restrict__ acc) {
    int t = blockIdx.x * blockDim.x + threadIdx.x;
    int e = t >> 5;
    if (e >= E) return;  // whole warp exits together (warp-aligned)
    int lane = threadIdx.x & 31;
    int s = __ldg(&src[e]);
    int d = __ldg(&dst[e]);
    float w4 = 0.f;
    if (lane < 4) {
        float ev = as_[s * 4 + lane] + ad_[d * 4 + lane];
        w4 = __expf(lrelu(ev));
        atomicAdd(&den[d * 4 + lane], w4);
    }
    float wh = __shfl_sync(0xffffffffu, w4, lane >> 3);  // head = lane/8
    float4 hv = *(const float4*)&h[s * 128 + lane * 4];
    red_add_v4(&acc[d * 128 + lane * 4], hv.x * wh, hv.y * wh, hv.z * wh, hv.w * wh);
}

// -------- edge pass, layer 2 (H=1, C=32): 8 threads per edge ----------------
__global__ void edge_pass1(const int* __restrict__ src, const int* __restrict__ dst, int E,
                           const float* __restrict__ as_, const float* __restrict__ ad_,
                           float* __restrict__ den, const float* __restrict__ h,
                           float* __restrict__ acc) {
    int t = blockIdx.x * blockDim.x + threadIdx.x;
    int e = t >> 3;
    bool valid = e < E;
    int ee = valid ? e : 0;
    int lane = threadIdx.x & 31;
    int sub = lane & 7;
    int s = __ldg(&src[ee]);
    int d = __ldg(&dst[ee]);
    float w = 0.f;
    if (sub == 0) {
        w = __expf(lrelu(as_[s] + ad_[d]));
        if (valid) atomicAdd(&den[d], w);
    }
    w = __shfl_sync(0xffffffffu, w, lane & 24);
    if (valid) {
        float4 hv = *(const float4*)&h[s * 32 + sub * 4];
        red_add_v4(&acc[d * 32 + sub * 4], hv.x * w, hv.y * w, hv.z * w, hv.w * w);
    }
}

// -------- finalize: out = acc/den + bias (optional relu) --------------------
template <int H, bool RELU>
__global__ void finalize_k(const float* __restrict__ acc, const float* __restrict__ den,
                           const float* __restrict__ bias, float* __restrict__ out, int n) {
    int t = blockIdx.x * blockDim.x + threadIdx.x;
    if (t >= n * H * 8) return;
    int g = t >> 3, sub = t & 7;
    int head = (H == 1) ? 0 : (g & (H - 1));
    float inv = 1.0f / den[g];
    float4 a = *(const float4*)&acc[g * 32 + sub * 4];
    float4 b = *(const float4*)&bias[head * 32 + sub * 4];
    float4 o;
    o.x = a.x * inv + b.x; o.y = a.y * inv + b.y;
    o.z = a.z * inv + b.z; o.w = a.w * inv + b.w;
    if (RELU) {
        o.x = fmaxf(o.x, 0.f); o.y = fmaxf(o.y, 0.f);
        o.z = fmaxf(o.z, 0.f); o.w = fmaxf(o.w, 0.f);
    }
    *(float4*)&out[g * 32 + sub * 4] = o;
}

// ---------------------------------------------------------------------------
extern "C" void kernel_launch(void* const* d_in, const int* in_sizes, int n_in,
                              void* d_out, int out_size) {
    const float* x    = (const float*)d_in[0];
    const int*   ei   = (const int*)d_in[1];
    const float* W1   = (const float*)d_in[2];
    const float* asr1 = (const float*)d_in[3];
    const float* adt1 = (const float*)d_in[4];
    const float* b1   = (const float*)d_in[5];
    const float* W2   = (const float*)d_in[6];
    const float* asr2 = (const float*)d_in[7];
    const float* adt2 = (const float*)d_in[8];
    const float* b2   = (const float*)d_in[9];
    float* out = (float*)d_out;

    const int n = in_sizes[0] / 128;
    const int E = in_sizes[1] / 2;
    const int* src = ei;
    const int* dst = ei + E;

    float *h1, *acc1, *hr, *as1, *ad1, *den1, *h2, *acc2, *as2, *ad2, *den2;
    cudaGetSymbolAddress((void**)&h1,   g_h1);
    cudaGetSymbolAddress((void**)&acc1, g_acc1);
    cudaGetSymbolAddress((void**)&hr,   g_hr);
    cudaGetSymbolAddress((void**)&as1,  g_as1);
    cudaGetSymbolAddress((void**)&ad1,  g_ad1);
    cudaGetSymbolAddress((void**)&den1, g_den1);
    cudaGetSymbolAddress((void**)&h2,   g_h2);
    cudaGetSymbolAddress((void**)&acc2, g_acc2);
    cudaGetSymbolAddress((void**)&as2,  g_as2);
    cudaGetSymbolAddress((void**)&ad2,  g_ad2);
    cudaGetSymbolAddress((void**)&den2, g_den2);

    const int nb64 = (n + 63) / 64;

    // ---- Layer 1: H=4, C=32 ----
    gemm_k128<64><<<dim3(nb64, 2), 256>>>(x, W1, h1, n, 128);
    {
        int t1 = n * 4 * 8;
        node_prep<4><<<(t1 + 255) / 256, 256>>>(h1, asr1, adt1, as1, ad1, den1, acc1, n);
        long long te = (long long)E * 32;
        edge_pass4<<<(unsigned)((te + 255) / 256), 256>>>(src, dst, E, as1, ad1, den1, h1, acc1);
        finalize_k<4, true><<<(t1 + 255) / 256, 256>>>(acc1, den1, b1, hr, n);
    }

    // ---- Layer 2: H=1, C=32 ----
    gemm_k128<32><<<dim3(nb64, 1), 128>>>(hr, W2, h2, n, 32);
    {
        int t2 = n * 1 * 8;
        node_prep<1><<<(t2 + 255) / 256, 256>>>(h2, asr2, adt2, as2, ad2, den2, acc2, n);
        long long te = (long long)E * 8;
        edge_pass1<<<(unsigned)((te + 255) / 256), 256>>>(src, dst, E, as2, ad2, den2, h2, acc2);
        finalize_k<1, false><<<(t2 + 255) / 256, 256>>>(acc2, den2, b2, out, n);
    }
}

// round 2
// speedup vs baseline: 1.1000x; 1.1000x over previous
#include <cuda_runtime.h>

#define MAXN 100000
#define MAXE 1600000

// ---------------- scratch (device globals, no allocation allowed) ----------
__device__ float g_h1[MAXN * 128];   // layer1 GEMM out [N, H*32]
__device__ float g_hr[MAXN * 128];   // layer1 output after softmax-agg + relu
__device__ float g_h2[MAXN * 32];    // layer2 GEMM out
__device__ float g_as1[MAXN * 4];
__device__ float g_ad1[MAXN * 4];
__device__ float g_as2[MAXN];
__device__ float g_ad2[MAXN];
__device__ int   g_deg[MAXN];        // per-dst degree (histogram)
__device__ int   g_off[MAXN + 1];    // CSR offsets
__device__ int   g_pos[MAXN];        // scatter cursors
__device__ int   g_ssrc[MAXE];       // src ids sorted by dst

__device__ __forceinline__ float lrelu(float x) { return x > 0.f ? x : 0.2f * x; }

// ---------------- GEMM: Y[n, nout] = X[n,128] @ W[128, nout] ---------------
template <int BN>
__global__ __launch_bounds__(16 * (BN / 4))
void gemm_k128(const float* __restrict__ X, const float* __restrict__ W,
               float* __restrict__ Y, int n, int nout) {
    constexpr int BM = 64, BK = 16;
    constexpr int T = 16 * (BN / 4);
    __shared__ float xs[BK][BM];
    __shared__ float ws[BK][BN];
    const int tid = threadIdx.x;
    const int row0 = blockIdx.x * BM;
    const int col0 = blockIdx.y * BN;
    const int tx = tid % (BN / 4);
    const int ty = tid / (BN / 4);
    float acc[4][4] = {};

    for (int k0 = 0; k0 < 128; k0 += BK) {
        #pragma unroll
        for (int idx = tid; idx < BM * BK / 4; idx += T) {
            int r = idx >> 2, q = idx & 3;
            int grow = row0 + r;
            float4 v = make_float4(0.f, 0.f, 0.f, 0.f);
            if (grow < n) v = *(const float4*)&X[grow * 128 + k0 + q * 4];
            xs[q * 4 + 0][r] = v.x; xs[q * 4 + 1][r] = v.y;
            xs[q * 4 + 2][r] = v.z; xs[q * 4 + 3][r] = v.w;
        }
        #pragma unroll
        for (int idx = tid; idx < BK * BN / 4; idx += T) {
            int r = idx / (BN / 4), c = idx % (BN / 4);
            *(float4*)&ws[r][c * 4] = *(const float4*)&W[(k0 + r) * nout + col0 + c * 4];
        }
        __syncthreads();
        #pragma unroll
        for (int kk = 0; kk < BK; kk++) {
            float4 a = *(const float4*)&xs[kk][ty * 4];
            float4 b = *(const float4*)&ws[kk][tx * 4];
            float av[4] = {a.x, a.y, a.z, a.w};
            float bv[4] = {b.x, b.y, b.z, b.w};
            #pragma unroll
            for (int i = 0; i < 4; i++)
                #pragma unroll
                for (int j = 0; j < 4; j++)
                    acc[i][j] += av[i] * bv[j];
        }
        __syncthreads();
    }
    #pragma unroll
    for (int i = 0; i < 4; i++) {
        int grow = row0 + ty * 4 + i;
        if (grow < n)
            *(float4*)&Y[grow * nout + col0 + tx * 4] =
                make_float4(acc[i][0], acc[i][1], acc[i][2], acc[i][3]);
    }
}

// ---------------- CSR build --------------------------------------------------
__global__ void hist_kernel(const int* __restrict__ dst, int E, int* __restrict__ deg) {
    int e = blockIdx.x * blockDim.x + threadIdx.x;
    if (e < E) atomicAdd(&deg[dst[e]], 1);
}

// single-block exclusive scan of deg[0..n) -> off[0..n]
__global__ __launch_bounds__(1024) void scan_kernel(const int* __restrict__ deg,
                                                    int* __restrict__ off, int n) {
    __shared__ int ssum[1024];
    int t = threadIdx.x;
    int ch = (n + 1023) / 1024;
    int c0 = t * ch;
    int c1 = min(c0 + ch, n);
    int s = 0;
    for (int i = c0; i < c1; i++) s += deg[i];
    ssum[t] = s;
    __syncthreads();
    #pragma unroll
    for (int o = 1; o < 1024; o <<= 1) {
        int v = (t >= o) ? ssum[t - o] : 0;
        __syncthreads();
        ssum[t] += v;
        __syncthreads();
    }
    int run = (t == 0) ? 0 : ssum[t - 1];
    for (int i = c0; i < c1; i++) { off[i] = run; run += deg[i]; }
    if (t == 1023) off[n] = ssum[1023];
}

__global__ void scatter_kernel(const int* __restrict__ src, const int* __restrict__ dst,
                               int E, int* __restrict__ pos, int* __restrict__ ssrc) {
    int e = blockIdx.x * blockDim.x + threadIdx.x;
    if (e < E) {
        int p = atomicAdd(&pos[dst[e]], 1);
        ssrc[p] = src[e];
    }
}

// -------- node dots: as_[g]=h.a_src, ad_[g]=h.a_dst (8 threads / group) -----
template <int H>
__global__ void node_dots(const float* __restrict__ h, const float* __restrict__ a_src,
                          const float* __restrict__ a_dst, float* __restrict__ as_,
                          float* __restrict__ ad_, int n) {
    int t = blockIdx.x * blockDim.x + threadIdx.x;
    int g = t >> 3;
    int sub = t & 7;
    if (g >= n * H) return;
    int head = (H == 1) ? 0 : (g & (H - 1));
    float4 hv = *(const float4*)&h[g * 32 + sub * 4];
    float4 av = *(const float4*)&a_src[head * 32 + sub * 4];
    float4 dv = *(const float4*)&a_dst[head * 32 + sub * 4];
    float s = hv.x * av.x + hv.y * av.y + hv.z * av.z + hv.w * av.w;
    float d = hv.x * dv.x + hv.y * dv.y + hv.z * dv.z + hv.w * dv.w;
    #pragma unroll
    for (int o = 4; o; o >>= 1) {
        s += __shfl_xor_sync(0xffffffffu, s, o);
        d += __shfl_xor_sync(0xffffffffu, d, o);
    }
    if (sub == 0) { as_[g] = s; ad_[g] = d; }
}

// -------- CSR aggregation, layer 1 (H=4, C=32): one warp per dst ------------
// Fuses: self-loop, softmax weights, denominator, normalize, bias, relu.
__global__ __launch_bounds__(256)
void agg4(const int* __restrict__ off, const int* __restrict__ ssrc,
          const float* __restrict__ h, const float* __restrict__ as_,
          const float* __restrict__ ad_, const float* __restrict__ bias,
          float* __restrict__ out, int n) {
    int warp = (blockIdx.x * blockDim.x + threadIdx.x) >> 5;
    if (warp >= n) return;
    int lane = threadIdx.x & 31;
    int d = warp;
    int ch = lane * 4;

    float adv = 0.f, asv = 0.f;
    if (lane < 4) { adv = ad_[d * 4 + lane]; asv = as_[d * 4 + lane]; }

    // self loop
    float4 hd = *(const float4*)&h[d * 128 + ch];
    float w = 0.f, den = 0.f;
    if (lane < 4) { w = __expf(lrelu(asv + adv)); den = w; }
    float wh = __shfl_sync(0xffffffffu, w, lane >> 3);
    float ax = wh * hd.x, ay = wh * hd.y, az = wh * hd.z, aw = wh * hd.w;

    int i = off[d], end = off[d + 1];
    for (; i + 1 < end; i += 2) {
        int s0 = __ldg(&ssrc[i]);
        int s1 = __ldg(&ssrc[i + 1]);
        float4 h0 = *(const float4*)&h[s0 * 128 + ch];
        float4 h1 = *(const float4*)&h[s1 * 128 + ch];
        float w0 = 0.f, w1 = 0.f;
        if (lane < 4) {
            w0 = __expf(lrelu(__ldg(&as_[s0 * 4 + lane]) + adv));
            w1 = __expf(lrelu(__ldg(&as_[s1 * 4 + lane]) + adv));
            den += w0 + w1;
        }
        float wh0 = __shfl_sync(0xffffffffu, w0, lane >> 3);
        float wh1 = __shfl_sync(0xffffffffu, w1, lane >> 3);
        ax += wh0 * h0.x + wh1 * h1.x;
        ay += wh0 * h0.y + wh1 * h1.y;
        az += wh0 * h0.z + wh1 * h1.z;
        aw += wh0 * h0.w + wh1 * h1.w;
    }
    if (i < end) {
        int s0 = __ldg(&ssrc[i]);
        float4 h0 = *(const float4*)&h[s0 * 128 + ch];
        float w0 = 0.f;
        if (lane < 4) {
            w0 = __expf(lrelu(__ldg(&as_[s0 * 4 + lane]) + adv));
            den += w0;
        }
        float wh0 = __shfl_sync(0xffffffffu, w0, lane >> 3);
        ax += wh0 * h0.x; ay += wh0 * h0.y; az += wh0 * h0.z; aw += wh0 * h0.w;
    }

    float inv = (lane < 4) ? 1.f / den : 0.f;
    float invh = __shfl_sync(0xffffffffu, inv, lane >> 3);
    float4 b = *(const float4*)&bias[ch];
    float4 o;
    o.x = fmaxf(ax * invh + b.x, 0.f);
    o.y = fmaxf(ay * invh + b.y, 0.f);
    o.z = fmaxf(az * invh + b.z, 0.f);
    o.w = fmaxf(aw * invh + b.w, 0.f);
    *(float4*)&out[d * 128 + ch] = o;
}

// -------- CSR aggregation, layer 2 (H=1, C=32): one warp per dst ------------
__global__ __launch_bounds__(256)
void agg1(const int* __restrict__ off, const int* __restrict__ ssrc,
          const float* __restrict__ h, const float* __restrict__ as_,
          const float* __restrict__ ad_, const float* __restrict__ bias,
          float* __restrict__ out, int n) {
    int warp = (blockIdx.x * blockDim.x + threadIdx.x) >> 5;
    if (warp >= n) return;
    int lane = threadIdx.x & 31;
    int d = warp;

    float adv = 0.f;
    if (lane == 0) adv = ad_[d];
    adv = __shfl_sync(0xffffffffu, adv, 0);

    // self loop
    float w = 0.f, den = 0.f;
    if (lane == 0) { w = __expf(lrelu(as_[d] + adv)); den = w; }
    float wb = __shfl_sync(0xffffffffu, w, 0);
    float acc = wb * h[d * 32 + lane];

    int i = off[d], end = off[d + 1];
    for (; i + 1 < end; i += 2) {
        int s0 = __ldg(&ssrc[i]);
        int s1 = __ldg(&ssrc[i + 1]);
        float h0 = __ldg(&h[s0 * 32 + lane]);
        float h1 = __ldg(&h[s1 * 32 + lane]);
        float w0 = 0.f, w1 = 0.f;
        if (lane == 0) {
            w0 = __expf(lrelu(__ldg(&as_[s0]) + adv));
            w1 = __expf(lrelu(__ldg(&as_[s1]) + adv));
            den += w0 + w1;
        }
        w0 = __shfl_sync(0xffffffffu, w0, 0);
        w1 = __shfl_sync(0xffffffffu, w1, 0);
        acc += w0 * h0 + w1 * h1;
    }
    if (i < end) {
        int s0 = __ldg(&ssrc[i]);
        float h0 = __ldg(&h[s0 * 32 + lane]);
        float w0 = 0.f;
        if (lane == 0) {
            w0 = __expf(lrelu(__ldg(&as_[s0]) + adv));
            den += w0;
        }
        w0 = __shfl_sync(0xffffffffu, w0, 0);
        acc += w0 * h0;
    }

    float inv = 0.f;
    if (lane == 0) inv = 1.f / den;
    inv = __shfl_sync(0xffffffffu, inv, 0);
    out[d * 32 + lane] = acc * inv + bias[lane];
}

// ---------------------------------------------------------------------------
extern "C" void kernel_launch(void* const* d_in, const int* in_sizes, int n_in,
                              void* d_out, int out_size) {
    const float* x    = (const float*)d_in[0];
    const int*   ei   = (const int*)d_in[1];
    const float* W1   = (const float*)d_in[2];
    const float* asr1 = (const float*)d_in[3];
    const float* adt1 = (const float*)d_in[4];
    const float* b1   = (const float*)d_in[5];
    const float* W2   = (const float*)d_in[6];
    const float* asr2 = (const float*)d_in[7];
    const float* adt2 = (const float*)d_in[8];
    const float* b2   = (const float*)d_in[9];
    float* out = (float*)d_out;

    const int n = in_sizes[0] / 128;
    const int E = in_sizes[1] / 2;
    const int* src = ei;
    const int* dst = ei + E;

    float *h1, *hr, *h2, *as1, *ad1, *as2, *ad2;
    int *deg, *off, *pos, *ssrc;
    cudaGetSymbolAddress((void**)&h1,   g_h1);
    cudaGetSymbolAddress((void**)&hr,   g_hr);
    cudaGetSymbolAddress((void**)&h2,   g_h2);
    cudaGetSymbolAddress((void**)&as1,  g_as1);
    cudaGetSymbolAddress((void**)&ad1,  g_ad1);
    cudaGetSymbolAddress((void**)&as2,  g_as2);
    cudaGetSymbolAddress((void**)&ad2,  g_ad2);
    cudaGetSymbolAddress((void**)&deg,  g_deg);
    cudaGetSymbolAddress((void**)&off,  g_off);
    cudaGetSymbolAddress((void**)&pos,  g_pos);
    cudaGetSymbolAddress((void**)&ssrc, g_ssrc);

    const int nb64 = (n + 63) / 64;
    const int eb = (E + 255) / 256;
    const int nwarp_blocks = (n * 32 + 255) / 256;

    // ---- CSR build (graph identical for both layers) ----
    cudaMemsetAsync(deg, 0, n * sizeof(int));
    hist_kernel<<<eb, 256>>>(dst, E, deg);
    scan_kernel<<<1, 1024>>>(deg, off, n);
    cudaMemcpyAsync(pos, off, n * sizeof(int), cudaMemcpyDeviceToDevice);
    scatter_kernel<<<eb, 256>>>(src, dst, E, pos, ssrc);

    // ---- Layer 1: H=4, C=32 ----
    gemm_k128<64><<<dim3(nb64, 2), 256>>>(x, W1, h1, n, 128);
    node_dots<4><<<(n * 4 * 8 + 255) / 256, 256>>>(h1, asr1, adt1, as1, ad1, n);
    agg4<<<nwarp_blocks, 256>>>(off, ssrc, h1, as1, ad1, b1, hr, n);

    // ---- Layer 2: H=1, C=32 ----
    gemm_k128<32><<<dim3(nb64, 1), 128>>>(hr, W2, h2, n, 32);
    node_dots<1><<<(n * 8 + 255) / 256, 256>>>(h2, asr2, adt2, as2, ad2, n);
    agg1<<<nwarp_blocks, 256>>>(off, ssrc, h2, as2, ad2, b2, out, n);
}

// round 3
// speedup vs baseline: 1.1840x; 1.0763x over previous
#include <cuda_runtime.h>
#include <cuda_fp16.h>

#define MAXN 100000
#define MAXE 1600000

// ---------------- scratch (device globals, no allocation allowed) ----------
__device__ float  g_h1[MAXN * 128];    // layer1 GEMM out fp32 [N,128]
__device__ __half g_h1h[MAXN * 128];   // layer1 GEMM out fp16 (for gathers)
__device__ float  g_hr[MAXN * 128];    // layer1 output after agg + relu
__device__ float  g_h2[MAXN * 32];     // layer2 GEMM out fp32
__device__ __half g_h2h[MAXN * 32];    // layer2 GEMM out fp16
__device__ float  g_as1[MAXN * 4];
__device__ float  g_ad1[MAXN * 4];
__device__ float  g_as2[MAXN];
__device__ float  g_ad2[MAXN];
__device__ int    g_deg[MAXN];
__device__ int    g_off[MAXN + 1];
__device__ int    g_pos[MAXN];
__device__ int    g_ssrc[MAXE];        // src ids sorted by dst

__device__ __forceinline__ float lrelu(float x) { return x > 0.f ? x : 0.2f * x; }

// ---------------- GEMM: Y = X[n,128] @ W[128,nout], dual fp32+fp16 out -----
// BM=128, BK=16, 128 threads, micro-tile 8 x (BN/8).
template <int BN>
__global__ __launch_bounds__(128)
void gemm_k128(const float* __restrict__ X, const float* __restrict__ W,
               float* __restrict__ Y, __half* __restrict__ Yh, int n, int nout) {
    constexpr int BM = 128, BK = 16;
    constexpr int TN = BN / 8;  // 8 (BN=64) or 4 (BN=32)
    __shared__ float xs[BK][BM];
    __shared__ float ws[BK][BN];
    const int tid = threadIdx.x;
    const int row0 = blockIdx.x * BM;
    const int col0 = blockIdx.y * BN;
    const int tx = tid & 7;    // 8 col-groups
    const int ty = tid >> 3;   // 16 row-groups of 8
    float acc[8][TN];
    #pragma unroll
    for (int i = 0; i < 8; i++)
        #pragma unroll
        for (int j = 0; j < TN; j++) acc[i][j] = 0.f;

    for (int k0 = 0; k0 < 128; k0 += BK) {
        // X tile (transposed): 128 rows x 16 k = 512 float4, 4 per thread
        #pragma unroll
        for (int p = 0; p < 4; p++) {
            int idx = tid + p * 128;
            int r = idx >> 2, q = idx & 3;
            int grow = row0 + r;
            float4 v = make_float4(0.f, 0.f, 0.f, 0.f);
            if (grow < n) v = *(const float4*)&X[grow * 128 + k0 + q * 4];
            xs[q * 4 + 0][r] = v.x; xs[q * 4 + 1][r] = v.y;
            xs[q * 4 + 2][r] = v.z; xs[q * 4 + 3][r] = v.w;
        }
        // W tile: 16 x BN
        #pragma unroll
        for (int idx = tid; idx < BK * BN / 4; idx += 128) {
            int r = idx / (BN / 4), c = idx % (BN / 4);
            *(float4*)&ws[r][c * 4] = *(const float4*)&W[(k0 + r) * nout + col0 + c * 4];
        }
        __syncthreads();
        #pragma unroll
        for (int kk = 0; kk < BK; kk++) {
            float a[8], b[TN];
            *(float4*)&a[0] = *(const float4*)&xs[kk][ty * 8];
            *(float4*)&a[4] = *(const float4*)&xs[kk][ty * 8 + 4];
            *(float4*)&b[0] = *(const float4*)&ws[kk][tx * TN];
            if (TN == 8) *(float4*)&b[4] = *(const float4*)&ws[kk][tx * TN + 4];
            #pragma unroll
            for (int i = 0; i < 8; i++)
                #pragma unroll
                for (int j = 0; j < TN; j++)
                    acc[i][j] += a[i] * b[j];
        }
        __syncthreads();
    }
    #pragma unroll
    for (int i = 0; i < 8; i++) {
        int grow = row0 + ty * 8 + i;
        if (grow >= n) continue;
        int cb = grow * nout + col0 + tx * TN;
        #pragma unroll
        for (int j = 0; j < TN; j += 4)
            *(float4*)&Y[cb + j] =
                make_float4(acc[i][j], acc[i][j+1], acc[i][j+2], acc[i][j+3]);
        __half hbuf[TN];
        #pragma unroll
        for (int j = 0; j < TN; j++) hbuf[j] = __float2half(acc[i][j]);
        if (TN == 8) *(uint4*)&Yh[cb] = *(uint4*)hbuf;
        else         *(uint2*)&Yh[cb] = *(uint2*)hbuf;
    }
}

// ---------------- CSR build --------------------------------------------------
__global__ void hist_kernel(const int* __restrict__ dst, int E, int* __restrict__ deg) {
    int e = blockIdx.x * blockDim.x + threadIdx.x;
    if (e < E) atomicAdd(&deg[dst[e]], 1);
}

__global__ __launch_bounds__(1024) void scan_kernel(const int* __restrict__ deg,
                                                    int* __restrict__ off, int n) {
    __shared__ int ssum[1024];
    int t = threadIdx.x;
    int ch = (n + 1023) / 1024;
    int c0 = t * ch;
    int c1 = min(c0 + ch, n);
    int s = 0;
    for (int i = c0; i < c1; i++) s += deg[i];
    ssum[t] = s;
    __syncthreads();
    #pragma unroll
    for (int o = 1; o < 1024; o <<= 1) {
        int v = (t >= o) ? ssum[t - o] : 0;
        __syncthreads();
        ssum[t] += v;
        __syncthreads();
    }
    int run = (t == 0) ? 0 : ssum[t - 1];
    for (int i = c0; i < c1; i++) { off[i] = run; run += deg[i]; }
    if (t == 1023) off[n] = ssum[1023];
}

__global__ void scatter_kernel(const int* __restrict__ src, const int* __restrict__ dst,
                               int E, int* __restrict__ pos, int* __restrict__ ssrc) {
    int e = blockIdx.x * blockDim.x + threadIdx.x;
    if (e < E) {
        int p = atomicAdd(&pos[dst[e]], 1);
        ssrc[p] = src[e];
    }
}

// -------- node dots ---------------------------------------------------------
template <int H>
__global__ void node_dots(const float* __restrict__ h, const float* __restrict__ a_src,
                          const float* __restrict__ a_dst, float* __restrict__ as_,
                          float* __restrict__ ad_, int n) {
    int t = blockIdx.x * blockDim.x + threadIdx.x;
    int g = t >> 3;
    int sub = t & 7;
    if (g >= n * H) return;
    int head = (H == 1) ? 0 : (g & (H - 1));
    float4 hv = *(const float4*)&h[g * 32 + sub * 4];
    float4 av = *(const float4*)&a_src[head * 32 + sub * 4];
    float4 dv = *(const float4*)&a_dst[head * 32 + sub * 4];
    float s = hv.x * av.x + hv.y * av.y + hv.z * av.z + hv.w * av.w;
    float d = hv.x * dv.x + hv.y * dv.y + hv.z * dv.z + hv.w * dv.w;
    #pragma unroll
    for (int o = 4; o; o >>= 1) {
        s += __shfl_xor_sync(0xffffffffu, s, o);
        d += __shfl_xor_sync(0xffffffffu, d, o);
    }
    if (sub == 0) { as_[g] = s; ad_[g] = d; }
}

// -------- CSR aggregation, layer 1 (H=4, C=32): one warp per dst ------------
__global__ __launch_bounds__(256)
void agg4(const int* __restrict__ off, const int* __restrict__ ssrc,
          const float* __restrict__ h, const __half* __restrict__ hh,
          const float* __restrict__ as_, const float* __restrict__ ad_,
          const float* __restrict__ bias, float* __restrict__ out, int n) {
    int d = (blockIdx.x * blockDim.x + threadIdx.x) >> 5;
    if (d >= n) return;
    int lane = threadIdx.x & 31;
    int ch = lane * 4;
    int hsel = lane >> 3;

    float adv = 0.f, asv = 0.f;
    if (lane < 4) { adv = ad_[d * 4 + lane]; asv = as_[d * 4 + lane]; }

    // self loop (exact fp32 row)
    float4 hd = *(const float4*)&h[d * 128 + ch];
    float w = 0.f, den = 0.f;
    if (lane < 4) { w = __expf(lrelu(asv + adv)); den = w; }
    float wh = __shfl_sync(0xffffffffu, w, hsel);
    float ax = wh * hd.x, ay = wh * hd.y, az = wh * hd.z, aw = wh * hd.w;

    int i = off[d], end = off[d + 1];
    for (; i + 3 < end; i += 4) {
        int s0 = __ldg(&ssrc[i]);
        int s1 = __ldg(&ssrc[i + 1]);
        int s2 = __ldg(&ssrc[i + 2]);
        int s3 = __ldg(&ssrc[i + 3]);
        uint2 r0 = __ldg((const uint2*)&hh[s0 * 128 + ch]);
        uint2 r1 = __ldg((const uint2*)&hh[s1 * 128 + ch]);
        uint2 r2 = __ldg((const uint2*)&hh[s2 * 128 + ch]);
        uint2 r3 = __ldg((const uint2*)&hh[s3 * 128 + ch]);
        float w0 = 0.f, w1 = 0.f, w2 = 0.f, w3 = 0.f;
        if (lane < 4) {
            w0 = __expf(lrelu(__ldg(&as_[s0 * 4 + lane]) + adv));
            w1 = __expf(lrelu(__ldg(&as_[s1 * 4 + lane]) + adv));
            w2 = __expf(lrelu(__ldg(&as_[s2 * 4 + lane]) + adv));
            w3 = __expf(lrelu(__ldg(&as_[s3 * 4 + lane]) + adv));
            den += (w0 + w1) + (w2 + w3);
        }
        float wh0 = __shfl_sync(0xffffffffu, w0, hsel);
        float wh1 = __shfl_sync(0xffffffffu, w1, hsel);
        float wh2 = __shfl_sync(0xffffffffu, w2, hsel);
        float wh3 = __shfl_sync(0xffffffffu, w3, hsel);
        float2 a0 = __half22float2(*(__half2*)&r0.x), b0 = __half22float2(*(__half2*)&r0.y);
        float2 a1 = __half22float2(*(__half2*)&r1.x), b1 = __half22float2(*(__half2*)&r1.y);
        float2 a2 = __half22float2(*(__half2*)&r2.x), b2 = __half22float2(*(__half2*)&r2.y);
        float2 a3 = __half22float2(*(__half2*)&r3.x), b3 = __half22float2(*(__half2*)&r3.y);
        ax += wh0 * a0.x + wh1 * a1.x + wh2 * a2.x + wh3 * a3.x;
        ay += wh0 * a0.y + wh1 * a1.y + wh2 * a2.y + wh3 * a3.y;
        az += wh0 * b0.x + wh1 * b1.x + wh2 * b2.x + wh3 * b3.x;
        aw += wh0 * b0.y + wh1 * b1.y + wh2 * b2.y + wh3 * b3.y;
    }
    for (; i < end; i++) {
        int s0 = __ldg(&ssrc[i]);
        uint2 r0 = __ldg((const uint2*)&hh[s0 * 128 + ch]);
        float w0 = 0.f;
        if (lane < 4) {
            w0 = __expf(lrelu(__ldg(&as_[s0 * 4 + lane]) + adv));
            den += w0;
        }
        float wh0 = __shfl_sync(0xffffffffu, w0, hsel);
        float2 a0 = __half22float2(*(__half2*)&r0.x), b0 = __half22float2(*(__half2*)&r0.y);
        ax += wh0 * a0.x; ay += wh0 * a0.y; az += wh0 * b0.x; aw += wh0 * b0.y;
    }

    float inv = (lane < 4) ? 1.f / den : 0.f;
    float invh = __shfl_sync(0xffffffffu, inv, hsel);
    float4 b = *(const float4*)&bias[ch];
    float4 o;
    o.x = fmaxf(ax * invh + b.x, 0.f);
    o.y = fmaxf(ay * invh + b.y, 0.f);
    o.z = fmaxf(az * invh + b.z, 0.f);
    o.w = fmaxf(aw * invh + b.w, 0.f);
    *(float4*)&out[d * 128 + ch] = o;
}

// -------- CSR aggregation, layer 2 (H=1, C=32): one warp per dst ------------
__global__ __launch_bounds__(256)
void agg1(const int* __restrict__ off, const int* __restrict__ ssrc,
          const float* __restrict__ h, const __half* __restrict__ hh,
          const float* __restrict__ as_, const float* __restrict__ ad_,
          const float* __restrict__ bias, float* __restrict__ out, int n) {
    int d = (blockIdx.x * blockDim.x + threadIdx.x) >> 5;
    if (d >= n) return;
    int lane = threadIdx.x & 31;

    float adv = 0.f;
    if (lane == 0) adv = ad_[d];
    adv = __shfl_sync(0xffffffffu, adv, 0);

    float w = 0.f, den = 0.f;
    if (lane == 0) { w = __expf(lrelu(as_[d] + adv)); den = w; }
    float wb = __shfl_sync(0xffffffffu, w, 0);
    float acc = wb * h[d * 32 + lane];

    int i = off[d], end = off[d + 1];
    for (; i + 3 < end; i += 4) {
        int s0 = __ldg(&ssrc[i]);
        int s1 = __ldg(&ssrc[i + 1]);
        int s2 = __ldg(&ssrc[i + 2]);
        int s3 = __ldg(&ssrc[i + 3]);
        float h0 = __half2float(__ldg(&hh[s0 * 32 + lane]));
        float h1 = __half2float(__ldg(&hh[s1 * 32 + lane]));
        float h2 = __half2float(__ldg(&hh[s2 * 32 + lane]));
        float h3 = __half2float(__ldg(&hh[s3 * 32 + lane]));
        float w0 = 0.f, w1 = 0.f, w2 = 0.f, w3 = 0.f;
        if (lane == 0) {
            w0 = __expf(lrelu(__ldg(&as_[s0]) + adv));
            w1 = __expf(lrelu(__ldg(&as_[s1]) + adv));
            w2 = __expf(lrelu(__ldg(&as_[s2]) + adv));
            w3 = __expf(lrelu(__ldg(&as_[s3]) + adv));
            den += (w0 + w1) + (w2 + w3);
        }
        w0 = __shfl_sync(0xffffffffu, w0, 0);
        w1 = __shfl_sync(0xffffffffu, w1, 0);
        w2 = __shfl_sync(0xffffffffu, w2, 0);
        w3 = __shfl_sync(0xffffffffu, w3, 0);
        acc += w0 * h0 + w1 * h1 + w2 * h2 + w3 * h3;
    }
    for (; i < end; i++) {
        int s0 = __ldg(&ssrc[i]);
        float h0 = __half2float(__ldg(&hh[s0 * 32 + lane]));
        float w0 = 0.f;
        if (lane == 0) {
            w0 = __expf(lrelu(__ldg(&as_[s0]) + adv));
            den += w0;
        }
        w0 = __shfl_sync(0xffffffffu, w0, 0);
        acc += w0 * h0;
    }

    float inv = 0.f;
    if (lane == 0) inv = 1.f / den;
    inv = __shfl_sync(0xffffffffu, inv, 0);
    out[d * 32 + lane] = acc * inv + bias[lane];
}

// ---------------------------------------------------------------------------
extern "C" void kernel_launch(void* const* d_in, const int* in_sizes, int n_in,
                              void* d_out, int out_size) {
    const float* x    = (const float*)d_in[0];
    const int*   ei   = (const int*)d_in[1];
    const float* W1   = (const float*)d_in[2];
    const float* asr1 = (const float*)d_in[3];
    const float* adt1 = (const float*)d_in[4];
    const float* b1   = (const float*)d_in[5];
    const float* W2   = (const float*)d_in[6];
    const float* asr2 = (const float*)d_in[7];
    const float* adt2 = (const float*)d_in[8];
    const float* b2   = (const float*)d_in[9];
    float* out = (float*)d_out;

    const int n = in_sizes[0] / 128;
    const int E = in_sizes[1] / 2;
    const int* src = ei;
    const int* dst = ei + E;

    float *h1, *hr, *h2, *as1, *ad1, *as2, *ad2;
    __half *h1h, *h2h;
    int *deg, *off, *pos, *ssrc;
    cudaGetSymbolAddress((void**)&h1,   g_h1);
    cudaGetSymbolAddress((void**)&h1h,  g_h1h);
    cudaGetSymbolAddress((void**)&hr,   g_hr);
    cudaGetSymbolAddress((void**)&h2,   g_h2);
    cudaGetSymbolAddress((void**)&h2h,  g_h2h);
    cudaGetSymbolAddress((void**)&as1,  g_as1);
    cudaGetSymbolAddress((void**)&ad1,  g_ad1);
    cudaGetSymbolAddress((void**)&as2,  g_as2);
    cudaGetSymbolAddress((void**)&ad2,  g_ad2);
    cudaGetSymbolAddress((void**)&deg,  g_deg);
    cudaGetSymbolAddress((void**)&off,  g_off);
    cudaGetSymbolAddress((void**)&pos,  g_pos);
    cudaGetSymbolAddress((void**)&ssrc, g_ssrc);

    const int nb128 = (n + 127) / 128;
    const int eb = (E + 255) / 256;
    const int nwarp_blocks = (n * 32 + 255) / 256;

    // ---- CSR build (graph identical for both layers) ----
    cudaMemsetAsync(deg, 0, n * sizeof(int));
    hist_kernel<<<eb, 256>>>(dst, E, deg);
    scan_kernel<<<1, 1024>>>(deg, off, n);
    cudaMemcpyAsync(pos, off, n * sizeof(int), cudaMemcpyDeviceToDevice);
    scatter_kernel<<<eb, 256>>>(src, dst, E, pos, ssrc);

    // ---- Layer 1: H=4, C=32 ----
    gemm_k128<64><<<dim3(nb128, 2), 128>>>(x, W1, h1, h1h, n, 128);
    node_dots<4><<<(n * 4 * 8 + 255) / 256, 256>>>(h1, asr1, adt1, as1, ad1, n);
    agg4<<<nwarp_blocks, 256>>>(off, ssrc, h1, h1h, as1, ad1, b1, hr, n);

    // ---- Layer 2: H=1, C=32 ----
    gemm_k128<32><<<dim3(nb128, 1), 128>>>(hr, W2, h2, h2h, n, 32);
    node_dots<1><<<(n * 8 + 255) / 256, 256>>>(h2, asr2, adt2, as2, ad2, n);
    agg1<<<nwarp_blocks, 256>>>(off, ssrc, h2, h2h, as2, ad2, b2, out, n);
}

// round 4
// speedup vs baseline: 1.4261x; 1.2045x over previous
#include <cuda_runtime.h>
#include <cuda_fp16.h>

#define MAXN 100000
#define MAXE 1600000

// ---------------- scratch (device globals, no allocation allowed) ----------
__device__ float  g_h1[MAXN * 128];
__device__ __half g_h1h[MAXN * 128];
__device__ float  g_hr[MAXN * 128];
__device__ float  g_h2[MAXN * 32];
__device__ __half g_h2h[MAXN * 32];
__device__ float  g_as1[MAXN * 4];
__device__ float  g_ad1[MAXN * 4];
__device__ float  g_as2[MAXN];
__device__ float  g_ad2[MAXN];
__device__ int    g_deg[MAXN];
__device__ int    g_off[MAXN + 1];
__device__ int    g_pos[MAXN];
__device__ int    g_ssrc[MAXE];

__device__ __forceinline__ float lrelu(float x) { return x > 0.f ? x : 0.2f * x; }

__device__ __forceinline__ unsigned tf32(float f) {
    unsigned u;
    asm("cvt.rna.tf32.f32 %0, %1;" : "=r"(u) : "f"(f));
    return u;
}

__device__ __forceinline__ void mma_tf32(float* d, const unsigned* a, unsigned b0, unsigned b1) {
    asm volatile(
        "mma.sync.aligned.m16n8k8.row.col.f32.tf32.tf32.f32 "
        "{%0,%1,%2,%3}, {%4,%5,%6,%7}, {%8,%9}, {%0,%1,%2,%3};"
        : "+f"(d[0]), "+f"(d[1]), "+f"(d[2]), "+f"(d[3])
        : "r"(a[0]), "r"(a[1]), "r"(a[2]), "r"(a[3]), "r"(b0), "r"(b1));
}

// ---------------- tf32 tensor-core GEMM: Y = X[n,128] @ W[128,nout] --------
// BM=128, BK=32, 128 threads (4 warps). Warp w: rows [w*32, w*32+32).
// Per warp: 2 m-tiles (m16) x NT n-tiles (n8). Dual fp32 + fp16 output.
template <int BN>
__global__ __launch_bounds__(128)
void gemm_tf32(const float* __restrict__ X, const float* __restrict__ W,
               float* __restrict__ Y, __half* __restrict__ Yh, int n, int nout) {
    constexpr int BM = 128, BK = 32;
    constexpr int NT = BN / 8;
    __shared__ float xs[BM][36];   // pad: bank(r,k) = (4r+k)%32, conflict-free frags
    __shared__ float ws[BK][72];   // pad: bank(k,c) = (8k+c)%32, conflict-free frags
    const int tid = threadIdx.x;
    const int warp = tid >> 5;
    const int lane = tid & 31;
    const int g = lane >> 2;     // 0..7
    const int tg = lane & 3;     // 0..3
    const int row0 = blockIdx.x * BM;
    const int col0 = blockIdx.y * BN;
    const int m0 = warp * 32;

    float acc[2][NT][4];
    #pragma unroll
    for (int mi = 0; mi < 2; mi++)
        #pragma unroll
        for (int ni = 0; ni < NT; ni++)
            #pragma unroll
            for (int q = 0; q < 4; q++) acc[mi][ni][q] = 0.f;

    for (int k0 = 0; k0 < 128; k0 += BK) {
        // X tile: 128 rows x 32 k (8 float4/thread)
        #pragma unroll
        for (int p = 0; p < 8; p++) {
            int idx = p * 128 + tid;
            int r = idx >> 3, q = idx & 7;
            int grow = row0 + r;
            float4 v = make_float4(0.f, 0.f, 0.f, 0.f);
            if (grow < n) v = *(const float4*)&X[grow * 128 + k0 + q * 4];
            *(float4*)&xs[r][q * 4] = v;
        }
        // W tile: 32 x BN
        #pragma unroll
        for (int idx = tid; idx < BK * BN / 4; idx += 128) {
            int r = idx / (BN / 4), c = idx % (BN / 4);
            *(float4*)&ws[r][c * 4] = *(const float4*)&W[(k0 + r) * nout + col0 + c * 4];
        }
        __syncthreads();
        #pragma unroll
        for (int kk = 0; kk < BK; kk += 8) {
            unsigned afrag[2][4];
            #pragma unroll
            for (int mi = 0; mi < 2; mi++) {
                int r = m0 + mi * 16 + g;
                afrag[mi][0] = tf32(xs[r][kk + tg]);
                afrag[mi][1] = tf32(xs[r + 8][kk + tg]);
                afrag[mi][2] = tf32(xs[r][kk + tg + 4]);
                afrag[mi][3] = tf32(xs[r + 8][kk + tg + 4]);
            }
            #pragma unroll
            for (int ni = 0; ni < NT; ni++) {
                unsigned b0 = tf32(ws[kk + tg][ni * 8 + g]);
                unsigned b1 = tf32(ws[kk + tg + 4][ni * 8 + g]);
                mma_tf32(acc[0][ni], afrag[0], b0, b1);
                mma_tf32(acc[1][ni], afrag[1], b0, b1);
            }
        }
        __syncthreads();
    }
    // epilogue: c0,c1 at (row g, cols 2tg,2tg+1); c2,c3 at (row g+8)
    #pragma unroll
    for (int mi = 0; mi < 2; mi++) {
        int ra = row0 + m0 + mi * 16 + g;
        int rb = ra + 8;
        #pragma unroll
        for (int ni = 0; ni < NT; ni++) {
            int c = col0 + ni * 8 + tg * 2;
            if (ra < n) {
                *(float2*)&Y[ra * nout + c] = make_float2(acc[mi][ni][0], acc[mi][ni][1]);
                *(__half2*)&Yh[ra * nout + c] =
                    __floats2half2_rn(acc[mi][ni][0], acc[mi][ni][1]);
            }
            if (rb < n) {
                *(float2*)&Y[rb * nout + c] = make_float2(acc[mi][ni][2], acc[mi][ni][3]);
                *(__half2*)&Yh[rb * nout + c] =
                    __floats2half2_rn(acc[mi][ni][2], acc[mi][ni][3]);
            }
        }
    }
}

// ---------------- CSR build --------------------------------------------------
__global__ void hist_kernel(const int* __restrict__ dst, int E, int* __restrict__ deg) {
    int e = blockIdx.x * blockDim.x + threadIdx.x;
    if (e < E) atomicAdd(&deg[dst[e]], 1);
}

__global__ __launch_bounds__(1024) void scan_kernel(const int* __restrict__ deg,
                                                    int* __restrict__ off, int n) {
    __shared__ int ssum[1024];
    int t = threadIdx.x;
    int ch = (n + 1023) / 1024;
    int c0 = t * ch;
    int c1 = min(c0 + ch, n);
    int s = 0;
    for (int i = c0; i < c1; i++) s += deg[i];
    ssum[t] = s;
    __syncthreads();
    #pragma unroll
    for (int o = 1; o < 1024; o <<= 1) {
        int v = (t >= o) ? ssum[t - o] : 0;
        __syncthreads();
        ssum[t] += v;
        __syncthreads();
    }
    int run = (t == 0) ? 0 : ssum[t - 1];
    for (int i = c0; i < c1; i++) { off[i] = run; run += deg[i]; }
    if (t == 1023) off[n] = ssum[1023];
}

__global__ void scatter_kernel(const int* __restrict__ src, const int* __restrict__ dst,
                               int E, int* __restrict__ pos, int* __restrict__ ssrc) {
    int e = blockIdx.x * blockDim.x + threadIdx.x;
    if (e < E) {
        int p = atomicAdd(&pos[dst[e]], 1);
        ssrc[p] = src[e];
    }
}

// -------- node dots ---------------------------------------------------------
template <int H>
__global__ void node_dots(const float* __restrict__ h, const float* __restrict__ a_src,
                          const float* __restrict__ a_dst, float* __restrict__ as_,
                          float* __restrict__ ad_, int n) {
    int t = blockIdx.x * blockDim.x + threadIdx.x;
    int g = t >> 3;
    int sub = t & 7;
    if (g >= n * H) return;
    int head = (H == 1) ? 0 : (g & (H - 1));
    float4 hv = *(const float4*)&h[g * 32 + sub * 4];
    float4 av = *(const float4*)&a_src[head * 32 + sub * 4];
    float4 dv = *(const float4*)&a_dst[head * 32 + sub * 4];
    float s = hv.x * av.x + hv.y * av.y + hv.z * av.z + hv.w * av.w;
    float d = hv.x * dv.x + hv.y * dv.y + hv.z * dv.z + hv.w * dv.w;
    #pragma unroll
    for (int o = 4; o; o >>= 1) {
        s += __shfl_xor_sync(0xffffffffu, s, o);
        d += __shfl_xor_sync(0xffffffffu, d, o);
    }
    if (sub == 0) { as_[g] = s; ad_[g] = d; }
}

// -------- CSR aggregation, layer 1 (H=4, C=32): one warp per dst ------------
__global__ __launch_bounds__(256)
void agg4(const int* __restrict__ off, const int* __restrict__ ssrc,
          const float* __restrict__ h, const __half* __restrict__ hh,
          const float* __restrict__ as_, const float* __restrict__ ad_,
          const float* __restrict__ bias, float* __restrict__ out, int n) {
    int d = (blockIdx.x * blockDim.x + threadIdx.x) >> 5;
    if (d >= n) return;
    int lane = threadIdx.x & 31;
    int ch = lane * 4;
    int hsel = lane >> 3;

    float adv = 0.f, asv = 0.f;
    if (lane < 4) { adv = ad_[d * 4 + lane]; asv = as_[d * 4 + lane]; }

    float4 hd = *(const float4*)&h[d * 128 + ch];
    float w = 0.f, den = 0.f;
    if (lane < 4) { w = __expf(lrelu(asv + adv)); den = w; }
    float wh = __shfl_sync(0xffffffffu, w, hsel);
    float ax = wh * hd.x, ay = wh * hd.y, az = wh * hd.z, aw = wh * hd.w;

    int i = off[d], end = off[d + 1];
    for (; i + 3 < end; i += 4) {
        int s0 = __ldg(&ssrc[i]);
        int s1 = __ldg(&ssrc[i + 1]);
        int s2 = __ldg(&ssrc[i + 2]);
        int s3 = __ldg(&ssrc[i + 3]);
        uint2 r0 = __ldg((const uint2*)&hh[s0 * 128 + ch]);
        uint2 r1 = __ldg((const uint2*)&hh[s1 * 128 + ch]);
        uint2 r2 = __ldg((const uint2*)&hh[s2 * 128 + ch]);
        uint2 r3 = __ldg((const uint2*)&hh[s3 * 128 + ch]);
        float w0 = 0.f, w1 = 0.f, w2 = 0.f, w3 = 0.f;
        if (lane < 4) {
            w0 = __expf(lrelu(__ldg(&as_[s0 * 4 + lane]) + adv));
            w1 = __expf(lrelu(__ldg(&as_[s1 * 4 + lane]) + adv));
            w2 = __expf(lrelu(__ldg(&as_[s2 * 4 + lane]) + adv));
            w3 = __expf(lrelu(__ldg(&as_[s3 * 4 + lane]) + adv));
            den += (w0 + w1) + (w2 + w3);
        }
        float wh0 = __shfl_sync(0xffffffffu, w0, hsel);
        float wh1 = __shfl_sync(0xffffffffu, w1, hsel);
        float wh2 = __shfl_sync(0xffffffffu, w2, hsel);
        float wh3 = __shfl_sync(0xffffffffu, w3, hsel);
        float2 a0 = __half22float2(*(__half2*)&r0.x), b0 = __half22float2(*(__half2*)&r0.y);
        float2 a1 = __half22float2(*(__half2*)&r1.x), b1 = __half22float2(*(__half2*)&r1.y);
        float2 a2 = __half22float2(*(__half2*)&r2.x), b2 = __half22float2(*(__half2*)&r2.y);
        float2 a3 = __half22float2(*(__half2*)&r3.x), b3 = __half22float2(*(__half2*)&r3.y);
        ax += wh0 * a0.x + wh1 * a1.x + wh2 * a2.x + wh3 * a3.x;
        ay += wh0 * a0.y + wh1 * a1.y + wh2 * a2.y + wh3 * a3.y;
        az += wh0 * b0.x + wh1 * b1.x + wh2 * b2.x + wh3 * b3.x;
        aw += wh0 * b0.y + wh1 * b1.y + wh2 * b2.y + wh3 * b3.y;
    }
    for (; i < end; i++) {
        int s0 = __ldg(&ssrc[i]);
        uint2 r0 = __ldg((const uint2*)&hh[s0 * 128 + ch]);
        float w0 = 0.f;
        if (lane < 4) {
            w0 = __expf(lrelu(__ldg(&as_[s0 * 4 + lane]) + adv));
            den += w0;
        }
        float wh0 = __shfl_sync(0xffffffffu, w0, hsel);
        float2 a0 = __half22float2(*(__half2*)&r0.x), b0 = __half22float2(*(__half2*)&r0.y);
        ax += wh0 * a0.x; ay += wh0 * a0.y; az += wh0 * b0.x; aw += wh0 * b0.y;
    }

    float inv = (lane < 4) ? 1.f / den : 0.f;
    float invh = __shfl_sync(0xffffffffu, inv, hsel);
    float4 b = *(const float4*)&bias[ch];
    float4 o;
    o.x = fmaxf(ax * invh + b.x, 0.f);
    o.y = fmaxf(ay * invh + b.y, 0.f);
    o.z = fmaxf(az * invh + b.z, 0.f);
    o.w = fmaxf(aw * invh + b.w, 0.f);
    *(float4*)&out[d * 128 + ch] = o;
}

// -------- CSR aggregation, layer 2 (H=1, C=32): one warp per dst ------------
__global__ __launch_bounds__(256)
void agg1(const int* __restrict__ off, const int* __restrict__ ssrc,
          const float* __restrict__ h, const __half* __restrict__ hh,
          const float* __restrict__ as_, const float* __restrict__ ad_,
          const float* __restrict__ bias, float* __restrict__ out, int n) {
    int d = (blockIdx.x * blockDim.x + threadIdx.x) >> 5;
    if (d >= n) return;
    int lane = threadIdx.x & 31;

    float adv = 0.f;
    if (lane == 0) adv = ad_[d];
    adv = __shfl_sync(0xffffffffu, adv, 0);

    float w = 0.f, den = 0.f;
    if (lane == 0) { w = __expf(lrelu(as_[d] + adv)); den = w; }
    float wb = __shfl_sync(0xffffffffu, w, 0);
    float acc = wb * h[d * 32 + lane];

    int i = off[d], end = off[d + 1];
    for (; i + 3 < end; i += 4) {
        int s0 = __ldg(&ssrc[i]);
        int s1 = __ldg(&ssrc[i + 1]);
        int s2 = __ldg(&ssrc[i + 2]);
        int s3 = __ldg(&ssrc[i + 3]);
        float h0 = __half2float(__ldg(&hh[s0 * 32 + lane]));
        float h1 = __half2float(__ldg(&hh[s1 * 32 + lane]));
        float h2 = __half2float(__ldg(&hh[s2 * 32 + lane]));
        float h3 = __half2float(__ldg(&hh[s3 * 32 + lane]));
        float w0 = 0.f, w1 = 0.f, w2 = 0.f, w3 = 0.f;
        if (lane == 0) {
            w0 = __expf(lrelu(__ldg(&as_[s0]) + adv));
            w1 = __expf(lrelu(__ldg(&as_[s1]) + adv));
            w2 = __expf(lrelu(__ldg(&as_[s2]) + adv));
            w3 = __expf(lrelu(__ldg(&as_[s3]) + adv));
            den += (w0 + w1) + (w2 + w3);
        }
        w0 = __shfl_sync(0xffffffffu, w0, 0);
        w1 = __shfl_sync(0xffffffffu, w1, 0);
        w2 = __shfl_sync(0xffffffffu, w2, 0);
        w3 = __shfl_sync(0xffffffffu, w3, 0);
        acc += w0 * h0 + w1 * h1 + w2 * h2 + w3 * h3;
    }
    for (; i < end; i++) {
        int s0 = __ldg(&ssrc[i]);
        float h0 = __half2float(__ldg(&hh[s0 * 32 + lane]));
        float w0 = 0.f;
        if (lane == 0) {
            w0 = __expf(lrelu(__ldg(&as_[s0]) + adv));
            den += w0;
        }
        w0 = __shfl_sync(0xffffffffu, w0, 0);
        acc += w0 * h0;
    }

    float inv = 0.f;
    if (lane == 0) inv = 1.f / den;
    inv = __shfl_sync(0xffffffffu, inv, 0);
    out[d * 32 + lane] = acc * inv + bias[lane];
}

// ---------------------------------------------------------------------------
extern "C" void kernel_launch(void* const* d_in, const int* in_sizes, int n_in,
                              void* d_out, int out_size) {
    const float* x    = (const float*)d_in[0];
    const int*   ei   = (const int*)d_in[1];
    const float* W1   = (const float*)d_in[2];
    const float* asr1 = (const float*)d_in[3];
    const float* adt1 = (const float*)d_in[4];
    const float* b1   = (const float*)d_in[5];
    const float* W2   = (const float*)d_in[6];
    const float* asr2 = (const float*)d_in[7];
    const float* adt2 = (const float*)d_in[8];
    const float* b2   = (const float*)d_in[9];
    float* out = (float*)d_out;

    const int n = in_sizes[0] / 128;
    const int E = in_sizes[1] / 2;
    const int* src = ei;
    const int* dst = ei + E;

    float *h1, *hr, *h2, *as1, *ad1, *as2, *ad2;
    __half *h1h, *h2h;
    int *deg, *off, *pos, *ssrc;
    cudaGetSymbolAddress((void**)&h1,   g_h1);
    cudaGetSymbolAddress((void**)&h1h,  g_h1h);
    cudaGetSymbolAddress((void**)&hr,   g_hr);
    cudaGetSymbolAddress((void**)&h2,   g_h2);
    cudaGetSymbolAddress((void**)&h2h,  g_h2h);
    cudaGetSymbolAddress((void**)&as1,  g_as1);
    cudaGetSymbolAddress((void**)&ad1,  g_ad1);
    cudaGetSymbolAddress((void**)&as2,  g_as2);
    cudaGetSymbolAddress((void**)&ad2,  g_ad2);
    cudaGetSymbolAddress((void**)&deg,  g_deg);
    cudaGetSymbolAddress((void**)&off,  g_off);
    cudaGetSymbolAddress((void**)&pos,  g_pos);
    cudaGetSymbolAddress((void**)&ssrc, g_ssrc);

    const int nb128 = (n + 127) / 128;
    const int eb = (E + 255) / 256;
    const int nwarp_blocks = (n * 32 + 255) / 256;

    // ---- CSR build (graph identical for both layers) ----
    cudaMemsetAsync(deg, 0, n * sizeof(int));
    hist_kernel<<<eb, 256>>>(dst, E, deg);
    scan_kernel<<<1, 1024>>>(deg, off, n);
    cudaMemcpyAsync(pos, off, n * sizeof(int), cudaMemcpyDeviceToDevice);
    scatter_kernel<<<eb, 256>>>(src, dst, E, pos, ssrc);

    // ---- Layer 1: H=4, C=32 ----
    gemm_tf32<64><<<dim3(nb128, 2), 128>>>(x, W1, h1, h1h, n, 128);
    node_dots<4><<<(n * 4 * 8 + 255) / 256, 256>>>(h1, asr1, adt1, as1, ad1, n);
    agg4<<<nwarp_blocks, 256>>>(off, ssrc, h1, h1h, as1, ad1, b1, hr, n);

    // ---- Layer 2: H=1, C=32 ----
    gemm_tf32<32><<<dim3(nb128, 1), 128>>>(hr, W2, h2, h2h, n, 32);
    node_dots<1><<<(n * 8 + 255) / 256, 256>>>(h2, asr2, adt2, as2, ad2, n);
    agg1<<<nwarp_blocks, 256>>>(off, ssrc, h2, h2h, as2, ad2, b2, out, n);
}

// round 5
// speedup vs baseline: 1.5086x; 1.0578x over previous
#include <cuda_runtime.h>
#include <cuda_fp16.h>

#define MAXN 100000
#define MAXE 1600000

// ---------------- scratch (device globals, no allocation allowed) ----------
__device__ __half g_h1h[MAXN * 128];   // layer1 GEMM out fp16
__device__ float  g_hr[MAXN * 128];    // layer1 output after agg + relu (gemm2 in)
__device__ __half g_h2h[MAXN * 32];    // layer2 GEMM out fp16
__device__ float  g_as1[MAXN * 4];
__device__ float  g_ad1[MAXN * 4];
__device__ float  g_as2[MAXN];
__device__ float  g_ad2[MAXN];
__device__ int    g_deg[MAXN];
__device__ int    g_off[MAXN + 1];
__device__ int    g_pos[MAXN];
__device__ int    g_ssrc[MAXE];

__device__ __forceinline__ float lrelu(float x) { return x > 0.f ? x : 0.2f * x; }

__device__ __forceinline__ unsigned tf32(float f) {
    unsigned u;
    asm("cvt.rna.tf32.f32 %0, %1;" : "=r"(u) : "f"(f));
    return u;
}

__device__ __forceinline__ void mma_tf32(float* d, const unsigned* a, unsigned b0, unsigned b1) {
    asm volatile(
        "mma.sync.aligned.m16n8k8.row.col.f32.tf32.tf32.f32 "
        "{%0,%1,%2,%3}, {%4,%5,%6,%7}, {%8,%9}, {%0,%1,%2,%3};"
        : "+f"(d[0]), "+f"(d[1]), "+f"(d[2]), "+f"(d[3])
        : "r"(a[0]), "r"(a[1]), "r"(a[2]), "r"(a[3]), "r"(b0), "r"(b1));
}

// ---------------- tf32 tensor-core GEMM: Yh = fp16(X[n,128] @ W[128,nout]) -
// BM=128, BK=32, 128 threads (4 warps). Warp w: rows [w*32, w*32+32).
template <int BN>
__global__ __launch_bounds__(128)
void gemm_tf32(const float* __restrict__ X, const float* __restrict__ W,
               __half* __restrict__ Yh, int n, int nout) {
    constexpr int BM = 128, BK = 32;
    constexpr int NT = BN / 8;
    __shared__ float xs[BM][36];
    __shared__ float ws[BK][72];
    const int tid = threadIdx.x;
    const int warp = tid >> 5;
    const int lane = tid & 31;
    const int g = lane >> 2;
    const int tg = lane & 3;
    const int row0 = blockIdx.x * BM;
    const int col0 = blockIdx.y * BN;
    const int m0 = warp * 32;

    float acc[2][NT][4];
    #pragma unroll
    for (int mi = 0; mi < 2; mi++)
        #pragma unroll
        for (int ni = 0; ni < NT; ni++)
            #pragma unroll
            for (int q = 0; q < 4; q++) acc[mi][ni][q] = 0.f;

    for (int k0 = 0; k0 < 128; k0 += BK) {
        #pragma unroll
        for (int p = 0; p < 8; p++) {
            int idx = p * 128 + tid;
            int r = idx >> 3, q = idx & 7;
            int grow = row0 + r;
            float4 v = make_float4(0.f, 0.f, 0.f, 0.f);
            if (grow < n) v = *(const float4*)&X[grow * 128 + k0 + q * 4];
            *(float4*)&xs[r][q * 4] = v;
        }
        #pragma unroll
        for (int idx = tid; idx < BK * BN / 4; idx += 128) {
            int r = idx / (BN / 4), c = idx % (BN / 4);
            *(float4*)&ws[r][c * 4] = *(const float4*)&W[(k0 + r) * nout + col0 + c * 4];
        }
        __syncthreads();
        #pragma unroll
        for (int kk = 0; kk < BK; kk += 8) {
            unsigned afrag[2][4];
            #pragma unroll
            for (int mi = 0; mi < 2; mi++) {
                int r = m0 + mi * 16 + g;
                afrag[mi][0] = tf32(xs[r][kk + tg]);
                afrag[mi][1] = tf32(xs[r + 8][kk + tg]);
                afrag[mi][2] = tf32(xs[r][kk + tg + 4]);
                afrag[mi][3] = tf32(xs[r + 8][kk + tg + 4]);
            }
            #pragma unroll
            for (int ni = 0; ni < NT; ni++) {
                unsigned b0 = tf32(ws[kk + tg][ni * 8 + g]);
                unsigned b1 = tf32(ws[kk + tg + 4][ni * 8 + g]);
                mma_tf32(acc[0][ni], afrag[0], b0, b1);
                mma_tf32(acc[1][ni], afrag[1], b0, b1);
            }
        }
        __syncthreads();
    }
    #pragma unroll
    for (int mi = 0; mi < 2; mi++) {
        int ra = row0 + m0 + mi * 16 + g;
        int rb = ra + 8;
        #pragma unroll
        for (int ni = 0; ni < NT; ni++) {
            int c = col0 + ni * 8 + tg * 2;
            if (ra < n)
                *(__half2*)&Yh[ra * nout + c] =
                    __floats2half2_rn(acc[mi][ni][0], acc[mi][ni][1]);
            if (rb < n)
                *(__half2*)&Yh[rb * nout + c] =
                    __floats2half2_rn(acc[mi][ni][2], acc[mi][ni][3]);
        }
    }
}

// ---------------- CSR build --------------------------------------------------
__global__ void hist_kernel(const int* __restrict__ dst, int E, int* __restrict__ deg) {
    int e = blockIdx.x * blockDim.x + threadIdx.x;
    if (e < E) atomicAdd(&deg[dst[e]], 1);
}

__global__ __launch_bounds__(1024) void scan_kernel(const int* __restrict__ deg,
                                                    int* __restrict__ off, int n) {
    __shared__ int ssum[1024];
    int t = threadIdx.x;
    int ch = (n + 1023) / 1024;
    int c0 = t * ch;
    int c1 = min(c0 + ch, n);
    int s = 0;
    for (int i = c0; i < c1; i++) s += deg[i];
    ssum[t] = s;
    __syncthreads();
    #pragma unroll
    for (int o = 1; o < 1024; o <<= 1) {
        int v = (t >= o) ? ssum[t - o] : 0;
        __syncthreads();
        ssum[t] += v;
        __syncthreads();
    }
    int run = (t == 0) ? 0 : ssum[t - 1];
    for (int i = c0; i < c1; i++) { off[i] = run; run += deg[i]; }
    if (t == 1023) off[n] = ssum[1023];
}

__global__ void scatter_kernel(const int* __restrict__ src, const int* __restrict__ dst,
                               int E, int* __restrict__ pos, int* __restrict__ ssrc) {
    int e = blockIdx.x * blockDim.x + threadIdx.x;
    if (e < E) {
        int p = atomicAdd(&pos[dst[e]], 1);
        ssrc[p] = src[e];
    }
}

// -------- node dots (fp16 h): 8 threads per (node,head) group ---------------
template <int H>
__global__ void node_dots(const __half* __restrict__ hh, const float* __restrict__ a_src,
                          const float* __restrict__ a_dst, float* __restrict__ as_,
                          float* __restrict__ ad_, int n) {
    int t = blockIdx.x * blockDim.x + threadIdx.x;
    int g = t >> 3;
    int sub = t & 7;
    if (g >= n * H) return;
    int head = (H == 1) ? 0 : (g & (H - 1));
    uint2 raw = *(const uint2*)&hh[g * 32 + sub * 4];
    float2 f0 = __half22float2(*(__half2*)&raw.x);
    float2 f1 = __half22float2(*(__half2*)&raw.y);
    float4 av = *(const float4*)&a_src[head * 32 + sub * 4];
    float4 dv = *(const float4*)&a_dst[head * 32 + sub * 4];
    float s = f0.x * av.x + f0.y * av.y + f1.x * av.z + f1.y * av.w;
    float d = f0.x * dv.x + f0.y * dv.y + f1.x * dv.z + f1.y * dv.w;
    #pragma unroll
    for (int o = 4; o; o >>= 1) {
        s += __shfl_xor_sync(0xffffffffu, s, o);
        d += __shfl_xor_sync(0xffffffffu, d, o);
    }
    if (sub == 0) { as_[g] = s; ad_[g] = d; }
}

// -------- CSR aggregation, layer 1 (H=4, C=32): one warp per dst ------------
__global__ __launch_bounds__(256)
void agg4(const int* __restrict__ off, const int* __restrict__ ssrc,
          const __half* __restrict__ hh,
          const float* __restrict__ as_, const float* __restrict__ ad_,
          const float* __restrict__ bias, float* __restrict__ out, int n) {
    int d = (blockIdx.x * blockDim.x + threadIdx.x) >> 5;
    if (d >= n) return;
    int lane = threadIdx.x & 31;
    int ch = lane * 4;
    int hsel = lane >> 3;

    float adv = 0.f, asv = 0.f;
    if (lane < 4) { adv = ad_[d * 4 + lane]; asv = as_[d * 4 + lane]; }

    // self loop
    uint2 rs = *(const uint2*)&hh[d * 128 + ch];
    float2 sa = __half22float2(*(__half2*)&rs.x), sb = __half22float2(*(__half2*)&rs.y);
    float w = 0.f, den = 0.f;
    if (lane < 4) { w = __expf(lrelu(asv + adv)); den = w; }
    float wh = __shfl_sync(0xffffffffu, w, hsel);
    float ax = wh * sa.x, ay = wh * sa.y, az = wh * sb.x, aw = wh * sb.y;

    int i = off[d], end = off[d + 1];
    for (; i + 3 < end; i += 4) {
        int s0 = __ldg(&ssrc[i]);
        int s1 = __ldg(&ssrc[i + 1]);
        int s2 = __ldg(&ssrc[i + 2]);
        int s3 = __ldg(&ssrc[i + 3]);
        uint2 r0 = __ldg((const uint2*)&hh[s0 * 128 + ch]);
        uint2 r1 = __ldg((const uint2*)&hh[s1 * 128 + ch]);
        uint2 r2 = __ldg((const uint2*)&hh[s2 * 128 + ch]);
        uint2 r3 = __ldg((const uint2*)&hh[s3 * 128 + ch]);
        float w0 = 0.f, w1 = 0.f, w2 = 0.f, w3 = 0.f;
        if (lane < 4) {
            w0 = __expf(lrelu(__ldg(&as_[s0 * 4 + lane]) + adv));
            w1 = __expf(lrelu(__ldg(&as_[s1 * 4 + lane]) + adv));
            w2 = __expf(lrelu(__ldg(&as_[s2 * 4 + lane]) + adv));
            w3 = __expf(lrelu(__ldg(&as_[s3 * 4 + lane]) + adv));
            den += (w0 + w1) + (w2 + w3);
        }
        float wh0 = __shfl_sync(0xffffffffu, w0, hsel);
        float wh1 = __shfl_sync(0xffffffffu, w1, hsel);
        float wh2 = __shfl_sync(0xffffffffu, w2, hsel);
        float wh3 = __shfl_sync(0xffffffffu, w3, hsel);
        float2 a0 = __half22float2(*(__half2*)&r0.x), b0 = __half22float2(*(__half2*)&r0.y);
        float2 a1 = __half22float2(*(__half2*)&r1.x), b1 = __half22float2(*(__half2*)&r1.y);
        float2 a2 = __half22float2(*(__half2*)&r2.x), b2 = __half22float2(*(__half2*)&r2.y);
        float2 a3 = __half22float2(*(__half2*)&r3.x), b3 = __half22float2(*(__half2*)&r3.y);
        ax += wh0 * a0.x + wh1 * a1.x + wh2 * a2.x + wh3 * a3.x;
        ay += wh0 * a0.y + wh1 * a1.y + wh2 * a2.y + wh3 * a3.y;
        az += wh0 * b0.x + wh1 * b1.x + wh2 * b2.x + wh3 * b3.x;
        aw += wh0 * b0.y + wh1 * b1.y + wh2 * b2.y + wh3 * b3.y;
    }
    for (; i < end; i++) {
        int s0 = __ldg(&ssrc[i]);
        uint2 r0 = __ldg((const uint2*)&hh[s0 * 128 + ch]);
        float w0 = 0.f;
        if (lane < 4) {
            w0 = __expf(lrelu(__ldg(&as_[s0 * 4 + lane]) + adv));
            den += w0;
        }
        float wh0 = __shfl_sync(0xffffffffu, w0, hsel);
        float2 a0 = __half22float2(*(__half2*)&r0.x), b0 = __half22float2(*(__half2*)&r0.y);
        ax += wh0 * a0.x; ay += wh0 * a0.y; az += wh0 * b0.x; aw += wh0 * b0.y;
    }

    float inv = (lane < 4) ? 1.f / den : 0.f;
    float invh = __shfl_sync(0xffffffffu, inv, hsel);
    float4 b = *(const float4*)&bias[ch];
    float4 o;
    o.x = fmaxf(ax * invh + b.x, 0.f);
    o.y = fmaxf(ay * invh + b.y, 0.f);
    o.z = fmaxf(az * invh + b.z, 0.f);
    o.w = fmaxf(aw * invh + b.w, 0.f);
    *(float4*)&out[d * 128 + ch] = o;
}

// -------- CSR aggregation, layer 2 (H=1, C=32): one warp per dst ------------
__global__ __launch_bounds__(256)
void agg1(const int* __restrict__ off, const int* __restrict__ ssrc,
          const __half* __restrict__ hh,
          const float* __restrict__ as_, const float* __restrict__ ad_,
          const float* __restrict__ bias, float* __restrict__ out, int n) {
    int d = (blockIdx.x * blockDim.x + threadIdx.x) >> 5;
    if (d >= n) return;
    int lane = threadIdx.x & 31;

    float adv = 0.f;
    if (lane == 0) adv = ad_[d];
    adv = __shfl_sync(0xffffffffu, adv, 0);

    float w = 0.f, den = 0.f;
    if (lane == 0) { w = __expf(lrelu(as_[d] + adv)); den = w; }
    float wb = __shfl_sync(0xffffffffu, w, 0);
    float acc = wb * __half2float(hh[d * 32 + lane]);

    int i = off[d], end = off[d + 1];
    for (; i + 3 < end; i += 4) {
        int s0 = __ldg(&ssrc[i]);
        int s1 = __ldg(&ssrc[i + 1]);
        int s2 = __ldg(&ssrc[i + 2]);
        int s3 = __ldg(&ssrc[i + 3]);
        float h0 = __half2float(__ldg(&hh[s0 * 32 + lane]));
        float h1 = __half2float(__ldg(&hh[s1 * 32 + lane]));
        float h2 = __half2float(__ldg(&hh[s2 * 32 + lane]));
        float h3 = __half2float(__ldg(&hh[s3 * 32 + lane]));
        float w0 = 0.f, w1 = 0.f, w2 = 0.f, w3 = 0.f;
        if (lane == 0) {
            w0 = __expf(lrelu(__ldg(&as_[s0]) + adv));
            w1 = __expf(lrelu(__ldg(&as_[s1]) + adv));
            w2 = __expf(lrelu(__ldg(&as_[s2]) + adv));
            w3 = __expf(lrelu(__ldg(&as_[s3]) + adv));
            den += (w0 + w1) + (w2 + w3);
        }
        w0 = __shfl_sync(0xffffffffu, w0, 0);
        w1 = __shfl_sync(0xffffffffu, w1, 0);
        w2 = __shfl_sync(0xffffffffu, w2, 0);
        w3 = __shfl_sync(0xffffffffu, w3, 0);
        acc += w0 * h0 + w1 * h1 + w2 * h2 + w3 * h3;
    }
    for (; i < end; i++) {
        int s0 = __ldg(&ssrc[i]);
        float h0 = __half2float(__ldg(&hh[s0 * 32 + lane]));
        float w0 = 0.f;
        if (lane == 0) {
            w0 = __expf(lrelu(__ldg(&as_[s0]) + adv));
            den += w0;
        }
        w0 = __shfl_sync(0xffffffffu, w0, 0);
        acc += w0 * h0;
    }

    float inv = 0.f;
    if (lane == 0) inv = 1.f / den;
    inv = __shfl_sync(0xffffffffu, inv, 0);
    out[d * 32 + lane] = acc * inv + bias[lane];
}

// ---------------------------------------------------------------------------
extern "C" void kernel_launch(void* const* d_in, const int* in_sizes, int n_in,
                              void* d_out, int out_size) {
    const float* x    = (const float*)d_in[0];
    const int*   ei   = (const int*)d_in[1];
    const float* W1   = (const float*)d_in[2];
    const float* asr1 = (const float*)d_in[3];
    const float* adt1 = (const float*)d_in[4];
    const float* b1   = (const float*)d_in[5];
    const float* W2   = (const float*)d_in[6];
    const float* asr2 = (const float*)d_in[7];
    const float* adt2 = (const float*)d_in[8];
    const float* b2   = (const float*)d_in[9];
    float* out = (float*)d_out;

    const int n = in_sizes[0] / 128;
    const int E = in_sizes[1] / 2;
    const int* src = ei;
    const int* dst = ei + E;

    float *hr, *as1, *ad1, *as2, *ad2;
    __half *h1h, *h2h;
    int *deg, *off, *pos, *ssrc;
    cudaGetSymbolAddress((void**)&h1h,  g_h1h);
    cudaGetSymbolAddress((void**)&hr,   g_hr);
    cudaGetSymbolAddress((void**)&h2h,  g_h2h);
    cudaGetSymbolAddress((void**)&as1,  g_as1);
    cudaGetSymbolAddress((void**)&ad1,  g_ad1);
    cudaGetSymbolAddress((void**)&as2,  g_as2);
    cudaGetSymbolAddress((void**)&ad2,  g_ad2);
    cudaGetSymbolAddress((void**)&deg,  g_deg);
    cudaGetSymbolAddress((void**)&off,  g_off);
    cudaGetSymbolAddress((void**)&pos,  g_pos);
    cudaGetSymbolAddress((void**)&ssrc, g_ssrc);

    // one-time side stream + events (host objects only; reused across calls)
    static cudaStream_t s2 = nullptr;
    static cudaEvent_t evFork = nullptr, evJoin = nullptr;
    if (!s2) {
        cudaStreamCreateWithFlags(&s2, cudaStreamNonBlocking);
        cudaEventCreateWithFlags(&evFork, cudaEventDisableTiming);
        cudaEventCreateWithFlags(&evJoin, cudaEventDisableTiming);
    }

    const int nb128 = (n + 127) / 128;
    const int eb = (E + 255) / 256;
    const int nwarp_blocks = (n * 32 + 255) / 256;

    // ---- fork: CSR build on side stream, overlapped with layer-1 GEMM ----
    cudaEventRecord(evFork, 0);
    cudaStreamWaitEvent(s2, evFork, 0);
    cudaMemsetAsync(deg, 0, n * sizeof(int), s2);
    hist_kernel<<<eb, 256, 0, s2>>>(dst, E, deg);
    scan_kernel<<<1, 1024, 0, s2>>>(deg, off, n);
    cudaMemcpyAsync(pos, off, n * sizeof(int), cudaMemcpyDeviceToDevice, s2);
    scatter_kernel<<<eb, 256, 0, s2>>>(src, dst, E, pos, ssrc);
    cudaEventRecord(evJoin, s2);

    // ---- main stream: layer-1 GEMM + dots (independent of CSR) ----
    gemm_tf32<64><<<dim3(nb128, 2), 128>>>(x, W1, h1h, n, 128);
    node_dots<4><<<(n * 4 * 8 + 255) / 256, 256>>>(h1h, asr1, adt1, as1, ad1, n);

    // ---- join: aggregation needs CSR ----
    cudaStreamWaitEvent(0, evJoin, 0);
    agg4<<<nwarp_blocks, 256>>>(off, ssrc, h1h, as1, ad1, b1, hr, n);

    // ---- Layer 2 ----
    gemm_tf32<32><<<dim3(nb128, 1), 128>>>(hr, W2, h2h, n, 32);
    node_dots<1><<<(n * 8 + 255) / 256, 256>>>(h2h, asr2, adt2, as2, ad2, n);
    agg1<<<nwarp_blocks, 256>>>(off, ssrc, h2h, as2, ad2, b2, out, n);
}

// round 6
// speedup vs baseline: 2.1175x; 1.4037x over previous
#include <cuda_runtime.h>
#include <cuda_fp16.h>

#define MAXN 100000
#define MAXE 1600000

// ---------------- scratch (device globals, no allocation allowed) ----------
__device__ __half g_h1h[MAXN * 128];
__device__ float  g_hr[MAXN * 128];
__device__ __half g_h2h[MAXN * 32];
__device__ float  g_as1[MAXN * 4];
__device__ float  g_ad1[MAXN * 4];
__device__ float  g_as2[MAXN];
__device__ float  g_ad2[MAXN];
__device__ int    g_deg[MAXN];
__device__ int    g_off[MAXN + 1];
__device__ int    g_pos[MAXN];
__device__ int    g_ssrc[MAXE];
__device__ int    g_bsum[512];

__device__ __forceinline__ float lrelu(float x) { return x > 0.f ? x : 0.2f * x; }

__device__ __forceinline__ unsigned tf32(float f) {
    unsigned u;
    asm("cvt.rna.tf32.f32 %0, %1;" : "=r"(u) : "f"(f));
    return u;
}

__device__ __forceinline__ void mma_tf32(float* d, const unsigned* a, unsigned b0, unsigned b1) {
    asm volatile(
        "mma.sync.aligned.m16n8k8.row.col.f32.tf32.tf32.f32 "
        "{%0,%1,%2,%3}, {%4,%5,%6,%7}, {%8,%9}, {%0,%1,%2,%3};"
        : "+f"(d[0]), "+f"(d[1]), "+f"(d[2]), "+f"(d[3])
        : "r"(a[0]), "r"(a[1]), "r"(a[2]), "r"(a[3]), "r"(b0), "r"(b1));
}

// ---------------- tf32 tensor-core GEMM: Yh = fp16(X[n,128] @ W[128,nout]) -
template <int BN>
__global__ __launch_bounds__(128)
void gemm_tf32(const float* __restrict__ X, const float* __restrict__ W,
               __half* __restrict__ Yh, int n, int nout) {
    constexpr int BM = 128, BK = 32;
    constexpr int NT = BN / 8;
    __shared__ float xs[BM][36];
    __shared__ float ws[BK][72];
    const int tid = threadIdx.x;
    const int warp = tid >> 5;
    const int lane = tid & 31;
    const int g = lane >> 2;
    const int tg = lane & 3;
    const int row0 = blockIdx.x * BM;
    const int col0 = blockIdx.y * BN;
    const int m0 = warp * 32;

    float acc[2][NT][4];
    #pragma unroll
    for (int mi = 0; mi < 2; mi++)
        #pragma unroll
        for (int ni = 0; ni < NT; ni++)
            #pragma unroll
            for (int q = 0; q < 4; q++) acc[mi][ni][q] = 0.f;

    for (int k0 = 0; k0 < 128; k0 += BK) {
        #pragma unroll
        for (int p = 0; p < 8; p++) {
            int idx = p * 128 + tid;
            int r = idx >> 3, q = idx & 7;
            int grow = row0 + r;
            float4 v = make_float4(0.f, 0.f, 0.f, 0.f);
            if (grow < n) v = *(const float4*)&X[grow * 128 + k0 + q * 4];
            *(float4*)&xs[r][q * 4] = v;
        }
        #pragma unroll
        for (int idx = tid; idx < BK * BN / 4; idx += 128) {
            int r = idx / (BN / 4), c = idx % (BN / 4);
            *(float4*)&ws[r][c * 4] = *(const float4*)&W[(k0 + r) * nout + col0 + c * 4];
        }
        __syncthreads();
        #pragma unroll
        for (int kk = 0; kk < BK; kk += 8) {
            unsigned afrag[2][4];
            #pragma unroll
            for (int mi = 0; mi < 2; mi++) {
                int r = m0 + mi * 16 + g;
                afrag[mi][0] = tf32(xs[r][kk + tg]);
                afrag[mi][1] = tf32(xs[r + 8][kk + tg]);
                afrag[mi][2] = tf32(xs[r][kk + tg + 4]);
                afrag[mi][3] = tf32(xs[r + 8][kk + tg + 4]);
            }
            #pragma unroll
            for (int ni = 0; ni < NT; ni++) {
                unsigned b0 = tf32(ws[kk + tg][ni * 8 + g]);
                unsigned b1 = tf32(ws[kk + tg + 4][ni * 8 + g]);
                mma_tf32(acc[0][ni], afrag[0], b0, b1);
                mma_tf32(acc[1][ni], afrag[1], b0, b1);
            }
        }
        __syncthreads();
    }
    #pragma unroll
    for (int mi = 0; mi < 2; mi++) {
        int ra = row0 + m0 + mi * 16 + g;
        int rb = ra + 8;
        #pragma unroll
        for (int ni = 0; ni < NT; ni++) {
            int c = col0 + ni * 8 + tg * 2;
            if (ra < n)
                *(__half2*)&Yh[ra * nout + c] =
                    __floats2half2_rn(acc[mi][ni][0], acc[mi][ni][1]);
            if (rb < n)
                *(__half2*)&Yh[rb * nout + c] =
                    __floats2half2_rn(acc[mi][ni][2], acc[mi][ni][3]);
        }
    }
}

// ---------------- CSR build --------------------------------------------------
__global__ void hist_kernel(const int* __restrict__ dst, int E, int* __restrict__ deg) {
    int e = blockIdx.x * blockDim.x + threadIdx.x;
    if (e < E) atomicAdd(&deg[dst[e]], 1);
}

// phase 1: per-block (256 elems) sums
__global__ __launch_bounds__(256)
void scan_part(const int* __restrict__ deg, int* __restrict__ bsum, int n) {
    int i = blockIdx.x * 256 + threadIdx.x;
    int v = (i < n) ? deg[i] : 0;
    #pragma unroll
    for (int o = 16; o; o >>= 1) v += __shfl_xor_sync(0xffffffffu, v, o);
    __shared__ int s[8];
    if ((threadIdx.x & 31) == 0) s[threadIdx.x >> 5] = v;
    __syncthreads();
    if (threadIdx.x == 0) {
        int t = 0;
        #pragma unroll
        for (int k = 0; k < 8; k++) t += s[k];
        bsum[blockIdx.x] = t;
    }
}

// phase 2: exclusive scan of block sums (nb <= 512), 1 block
__global__ __launch_bounds__(512)
void scan_mid(int* __restrict__ bsum, int nb) {
    __shared__ int s[512];
    int t = threadIdx.x;
    int v = (t < nb) ? bsum[t] : 0;
    s[t] = v;
    __syncthreads();
    #pragma unroll
    for (int o = 1; o < 512; o <<= 1) {
        int u = (t >= o) ? s[t - o] : 0;
        __syncthreads();
        s[t] += u;
        __syncthreads();
    }
    if (t < nb) bsum[t] = s[t] - v;  // exclusive
}

// phase 3: block-local exclusive scan + base; writes off and pos
__global__ __launch_bounds__(256)
void scan_final(const int* __restrict__ deg, const int* __restrict__ bsum,
                int* __restrict__ off, int* __restrict__ pos, int n) {
    int i = blockIdx.x * 256 + threadIdx.x;
    int lane = threadIdx.x & 31;
    int wid = threadIdx.x >> 5;
    int v = (i < n) ? deg[i] : 0;
    // warp inclusive scan
    int incl = v;
    #pragma unroll
    for (int o = 1; o < 32; o <<= 1) {
        int u = __shfl_up_sync(0xffffffffu, incl, o);
        if (lane >= o) incl += u;
    }
    __shared__ int wsum[8];
    if (lane == 31) wsum[wid] = incl;
    __syncthreads();
    int wbase = 0;
    #pragma unroll
    for (int k = 0; k < 8; k++) wbase += (k < wid) ? wsum[k] : 0;
    int excl = bsum[blockIdx.x] + wbase + incl - v;
    if (i < n) { off[i] = excl; pos[i] = excl; }
    if (i == n - 1) off[n] = excl + v;
}

__global__ void scatter_kernel(const int* __restrict__ src, const int* __restrict__ dst,
                               int E, int* __restrict__ pos, int* __restrict__ ssrc) {
    int e = blockIdx.x * blockDim.x + threadIdx.x;
    if (e < E) {
        int p = atomicAdd(&pos[dst[e]], 1);
        ssrc[p] = src[e];
    }
}

// -------- node dots (fp16 h): 8 threads per (node,head) group ---------------
template <int H>
__global__ void node_dots(const __half* __restrict__ hh, const float* __restrict__ a_src,
                          const float* __restrict__ a_dst, float* __restrict__ as_,
                          float* __restrict__ ad_, int n) {
    int t = blockIdx.x * blockDim.x + threadIdx.x;
    int g = t >> 3;
    int sub = t & 7;
    if (g >= n * H) return;
    int head = (H == 1) ? 0 : (g & (H - 1));
    uint2 raw = *(const uint2*)&hh[g * 32 + sub * 4];
    float2 f0 = __half22float2(*(__half2*)&raw.x);
    float2 f1 = __half22float2(*(__half2*)&raw.y);
    float4 av = *(const float4*)&a_src[head * 32 + sub * 4];
    float4 dv = *(const float4*)&a_dst[head * 32 + sub * 4];
    float s = f0.x * av.x + f0.y * av.y + f1.x * av.z + f1.y * av.w;
    float d = f0.x * dv.x + f0.y * dv.y + f1.x * dv.z + f1.y * dv.w;
    #pragma unroll
    for (int o = 4; o; o >>= 1) {
        s += __shfl_xor_sync(0xffffffffu, s, o);
        d += __shfl_xor_sync(0xffffffffu, d, o);
    }
    if (sub == 0) { as_[g] = s; ad_[g] = d; }
}

// -------- CSR aggregation, layer 1 (H=4, C=32): one warp per dst ------------
// exp distributed over 16 lanes: lane = edge*4 + head (1 LDG + 1 expf / 4 edges)
__global__ __launch_bounds__(256)
void agg4(const int* __restrict__ off, const int* __restrict__ ssrc,
          const __half* __restrict__ hh,
          const float* __restrict__ as_, const float* __restrict__ ad_,
          const float* __restrict__ bias, float* __restrict__ out, int n) {
    int d = (blockIdx.x * blockDim.x + threadIdx.x) >> 5;
    if (d >= n) return;
    int lane = threadIdx.x & 31;
    int ch = lane * 4;
    int hsel = lane >> 3;

    float adv = 0.f, asv = 0.f;
    if (lane < 4) { adv = ad_[d * 4 + lane]; asv = as_[d * 4 + lane]; }
    float advl = __shfl_sync(0xffffffffu, adv, lane & 3);  // adv for head lane&3

    // self loop
    uint2 rs = *(const uint2*)&hh[d * 128 + ch];
    float2 sa = __half22float2(*(__half2*)&rs.x), sb = __half22float2(*(__half2*)&rs.y);
    float w = 0.f, den = 0.f;
    if (lane < 4) { w = __expf(lrelu(asv + adv)); den = w; }
    float wh = __shfl_sync(0xffffffffu, w, hsel);
    float ax = wh * sa.x, ay = wh * sa.y, az = wh * sb.x, aw = wh * sb.y;

    int i = off[d], end = off[d + 1];
    for (; i + 3 < end; i += 4) {
        int s0 = __ldg(&ssrc[i]);
        int s1 = __ldg(&ssrc[i + 1]);
        int s2 = __ldg(&ssrc[i + 2]);
        int s3 = __ldg(&ssrc[i + 3]);
        uint2 r0 = __ldg((const uint2*)&hh[s0 * 128 + ch]);
        uint2 r1 = __ldg((const uint2*)&hh[s1 * 128 + ch]);
        uint2 r2 = __ldg((const uint2*)&hh[s2 * 128 + ch]);
        uint2 r3 = __ldg((const uint2*)&hh[s3 * 128 + ch]);
        // lanes 0..15: edge = lane>>2, head = lane&3
        float we = 0.f;
        if (lane < 16) {
            int e = lane >> 2;
            int se = (e == 0) ? s0 : (e == 1) ? s1 : (e == 2) ? s2 : s3;
            float av = __ldg(&as_[se * 4 + (lane & 3)]);
            we = __expf(lrelu(av + advl));
        }
        // per-head denominator sums (lanes 0..3 end up with totals)
        float wsum = we + __shfl_xor_sync(0xffffffffu, we, 4);
        wsum += __shfl_xor_sync(0xffffffffu, wsum, 8);
        if (lane < 4) den += wsum;
        // per-edge weight for this lane's head
        float wh0 = __shfl_sync(0xffffffffu, we, 0 + hsel);
        float wh1 = __shfl_sync(0xffffffffu, we, 4 + hsel);
        float wh2 = __shfl_sync(0xffffffffu, we, 8 + hsel);
        float wh3 = __shfl_sync(0xffffffffu, we, 12 + hsel);
        float2 a0 = __half22float2(*(__half2*)&r0.x), b0 = __half22float2(*(__half2*)&r0.y);
        float2 a1 = __half22float2(*(__half2*)&r1.x), b1 = __half22float2(*(__half2*)&r1.y);
        float2 a2 = __half22float2(*(__half2*)&r2.x), b2 = __half22float2(*(__half2*)&r2.y);
        float2 a3 = __half22float2(*(__half2*)&r3.x), b3 = __half22float2(*(__half2*)&r3.y);
        ax += wh0 * a0.x + wh1 * a1.x + wh2 * a2.x + wh3 * a3.x;
        ay += wh0 * a0.y + wh1 * a1.y + wh2 * a2.y + wh3 * a3.y;
        az += wh0 * b0.x + wh1 * b1.x + wh2 * b2.x + wh3 * b3.x;
        aw += wh0 * b0.y + wh1 * b1.y + wh2 * b2.y + wh3 * b3.y;
    }
    for (; i < end; i++) {
        int s0 = __ldg(&ssrc[i]);
        uint2 r0 = __ldg((const uint2*)&hh[s0 * 128 + ch]);
        float w0 = 0.f;
        if (lane < 4) {
            w0 = __expf(lrelu(__ldg(&as_[s0 * 4 + lane]) + adv));
            den += w0;
        }
        float wh0 = __shfl_sync(0xffffffffu, w0, hsel);
        float2 a0 = __half22float2(*(__half2*)&r0.x), b0 = __half22float2(*(__half2*)&r0.y);
        ax += wh0 * a0.x; ay += wh0 * a0.y; az += wh0 * b0.x; aw += wh0 * b0.y;
    }

    float inv = (lane < 4) ? 1.f / den : 0.f;
    float invh = __shfl_sync(0xffffffffu, inv, hsel);
    float4 b = *(const float4*)&bias[ch];
    float4 o;
    o.x = fmaxf(ax * invh + b.x, 0.f);
    o.y = fmaxf(ay * invh + b.y, 0.f);
    o.z = fmaxf(az * invh + b.z, 0.f);
    o.w = fmaxf(aw * invh + b.w, 0.f);
    *(float4*)&out[d * 128 + ch] = o;
}

// -------- CSR aggregation, layer 2 (H=1, C=32): one warp per dst ------------
__global__ __launch_bounds__(256)
void agg1(const int* __restrict__ off, const int* __restrict__ ssrc,
          const __half* __restrict__ hh,
          const float* __restrict__ as_, const float* __restrict__ ad_,
          const float* __restrict__ bias, float* __restrict__ out, int n) {
    int d = (blockIdx.x * blockDim.x + threadIdx.x) >> 5;
    if (d >= n) return;
    int lane = threadIdx.x & 31;

    float adv = 0.f;
    if (lane == 0) adv = ad_[d];
    adv = __shfl_sync(0xffffffffu, adv, 0);

    float w = 0.f, den = 0.f;
    if (lane == 0) { w = __expf(lrelu(as_[d] + adv)); den = w; }
    float wb = __shfl_sync(0xffffffffu, w, 0);
    float acc = wb * __half2float(hh[d * 32 + lane]);

    int i = off[d], end = off[d + 1];
    for (; i + 3 < end; i += 4) {
        int s0 = __ldg(&ssrc[i]);
        int s1 = __ldg(&ssrc[i + 1]);
        int s2 = __ldg(&ssrc[i + 2]);
        int s3 = __ldg(&ssrc[i + 3]);
        float h0 = __half2float(__ldg(&hh[s0 * 32 + lane]));
        float h1 = __half2float(__ldg(&hh[s1 * 32 + lane]));
        float h2 = __half2float(__ldg(&hh[s2 * 32 + lane]));
        float h3 = __half2float(__ldg(&hh[s3 * 32 + lane]));
        // lanes 0..3: one exp each
        float we = 0.f;
        if (lane < 4) {
            int se = (lane == 0) ? s0 : (lane == 1) ? s1 : (lane == 2) ? s2 : s3;
            we = __expf(lrelu(__ldg(&as_[se]) + adv));
        }
        float wsum = we + __shfl_xor_sync(0xffffffffu, we, 1);
        wsum += __shfl_xor_sync(0xffffffffu, wsum, 2);
        if (lane == 0) den += wsum;
        float w0 = __shfl_sync(0xffffffffu, we, 0);
        float w1 = __shfl_sync(0xffffffffu, we, 1);
        float w2 = __shfl_sync(0xffffffffu, we, 2);
        float w3 = __shfl_sync(0xffffffffu, we, 3);
        acc += w0 * h0 + w1 * h1 + w2 * h2 + w3 * h3;
    }
    for (; i < end; i++) {
        int s0 = __ldg(&ssrc[i]);
        float h0 = __half2float(__ldg(&hh[s0 * 32 + lane]));
        float w0 = 0.f;
        if (lane == 0) {
            w0 = __expf(lrelu(__ldg(&as_[s0]) + adv));
            den += w0;
        }
        w0 = __shfl_sync(0xffffffffu, w0, 0);
        acc += w0 * h0;
    }

    float inv = 0.f;
    if (lane == 0) inv = 1.f / den;
    inv = __shfl_sync(0xffffffffu, inv, 0);
    out[d * 32 + lane] = acc * inv + bias[lane];
}

// ---------------------------------------------------------------------------
extern "C" void kernel_launch(void* const* d_in, const int* in_sizes, int n_in,
                              void* d_out, int out_size) {
    const float* x    = (const float*)d_in[0];
    const int*   ei   = (const int*)d_in[1];
    const float* W1   = (const float*)d_in[2];
    const float* asr1 = (const float*)d_in[3];
    const float* adt1 = (const float*)d_in[4];
    const float* b1   = (const float*)d_in[5];
    const float* W2   = (const float*)d_in[6];
    const float* asr2 = (const float*)d_in[7];
    const float* adt2 = (const float*)d_in[8];
    const float* b2   = (const float*)d_in[9];
    float* out = (float*)d_out;

    const int n = in_sizes[0] / 128;
    const int E = in_sizes[1] / 2;
    const int* src = ei;
    const int* dst = ei + E;

    float *hr, *as1, *ad1, *as2, *ad2;
    __half *h1h, *h2h;
    int *deg, *off, *pos, *ssrc, *bsum;
    cudaGetSymbolAddress((void**)&h1h,  g_h1h);
    cudaGetSymbolAddress((void**)&hr,   g_hr);
    cudaGetSymbolAddress((void**)&h2h,  g_h2h);
    cudaGetSymbolAddress((void**)&as1,  g_as1);
    cudaGetSymbolAddress((void**)&ad1,  g_ad1);
    cudaGetSymbolAddress((void**)&as2,  g_as2);
    cudaGetSymbolAddress((void**)&ad2,  g_ad2);
    cudaGetSymbolAddress((void**)&deg,  g_deg);
    cudaGetSymbolAddress((void**)&off,  g_off);
    cudaGetSymbolAddress((void**)&pos,  g_pos);
    cudaGetSymbolAddress((void**)&ssrc, g_ssrc);
    cudaGetSymbolAddress((void**)&bsum, g_bsum);

    static cudaStream_t s2 = nullptr;
    static cudaEvent_t evFork = nullptr, evJoin = nullptr;
    if (!s2) {
        cudaStreamCreateWithFlags(&s2, cudaStreamNonBlocking);
        cudaEventCreateWithFlags(&evFork, cudaEventDisableTiming);
        cudaEventCreateWithFlags(&evJoin, cudaEventDisableTiming);
    }

    const int nb128 = (n + 127) / 128;
    const int eb = (E + 255) / 256;
    const int nwarp_blocks = (n * 32 + 255) / 256;
    const int nscan = (n + 255) / 256;

    // ---- fork: CSR build on side stream ----
    cudaEventRecord(evFork, 0);
    cudaStreamWaitEvent(s2, evFork, 0);
    cudaMemsetAsync(deg, 0, n * sizeof(int), s2);
    hist_kernel<<<eb, 256, 0, s2>>>(dst, E, deg);
    scan_part<<<nscan, 256, 0, s2>>>(deg, bsum, n);
    scan_mid<<<1, 512, 0, s2>>>(bsum, nscan);
    scan_final<<<nscan, 256, 0, s2>>>(deg, bsum, off, pos, n);
    scatter_kernel<<<eb, 256, 0, s2>>>(src, dst, E, pos, ssrc);
    cudaEventRecord(evJoin, s2);

    // ---- main stream: layer-1 GEMM + dots ----
    gemm_tf32<64><<<dim3(nb128, 2), 128>>>(x, W1, h1h, n, 128);
    node_dots<4><<<(n * 4 * 8 + 255) / 256, 256>>>(h1h, asr1, adt1, as1, ad1, n);

    // ---- join ----
    cudaStreamWaitEvent(0, evJoin, 0);
    agg4<<<nwarp_blocks, 256>>>(off, ssrc, h1h, as1, ad1, b1, hr, n);

    // ---- Layer 2 ----
    gemm_tf32<32><<<dim3(nb128, 1), 128>>>(hr, W2, h2h, n, 32);
    node_dots<1><<<(n * 8 + 255) / 256, 256>>>(h2h, asr2, adt2, as2, ad2, n);
    agg1<<<nwarp_blocks, 256>>>(off, ssrc, h2h, as2, ad2, b2, out, n);
}